// round 1
// baseline (speedup 1.0000x reference)
#include <cuda_runtime.h>

#define B_  4
#define T_  2048
#define D_  1024
#define H_  16
#define HD_ 64
#define M_  (B_ * T_)   // 8192 rows for all projections

// Scratch (device globals — no allocations allowed)
__device__ float g_q[B_ * H_ * T_ * HD_];   // [b,h,t,hd]
__device__ float g_k[B_ * H_ * T_ * HD_];
__device__ float g_v[B_ * H_ * T_ * HD_];
__device__ float g_o[M_ * D_];              // attention output, [b*t, h*hd]

// ---------------------------------------------------------------------------
// GEMM: Y = X[M,K] @ W[N,K]^T + bias[N]
// HEADS=1: scatter into [b,h,t,hd] layout. HEADS=0: row-major [M,N].
// Tile 128x128x16, 256 threads, 8x8 per thread.
// ---------------------------------------------------------------------------
template <int HEADS>
__global__ __launch_bounds__(256, 2)
void gemm_bias_kernel(const float* __restrict__ X,
                      const float* __restrict__ W,
                      const float* __restrict__ bias,
                      float* __restrict__ Y)
{
    const int Kd = D_;
    __shared__ float As[16][128];
    __shared__ float Bs[16][128];

    const int m0 = blockIdx.y * 128;
    const int n0 = blockIdx.x * 128;
    const int t  = threadIdx.x;
    const int tx = t & 15;
    const int ty = t >> 4;

    float acc[8][8];
#pragma unroll
    for (int i = 0; i < 8; i++)
#pragma unroll
        for (int j = 0; j < 8; j++) acc[i][j] = 0.f;

    for (int k0 = 0; k0 < Kd; k0 += 16) {
#pragma unroll
        for (int ff = 0; ff < 2; ff++) {
            int f   = t + ff * 256;          // 0..511
            int row = f >> 2;                // 0..127
            int kq  = (f & 3) << 2;          // 0,4,8,12
            float4 va = *(const float4*)(X + (size_t)(m0 + row) * Kd + k0 + kq);
            As[kq + 0][row] = va.x; As[kq + 1][row] = va.y;
            As[kq + 2][row] = va.z; As[kq + 3][row] = va.w;
            float4 vb = *(const float4*)(W + (size_t)(n0 + row) * Kd + k0 + kq);
            Bs[kq + 0][row] = vb.x; Bs[kq + 1][row] = vb.y;
            Bs[kq + 2][row] = vb.z; Bs[kq + 3][row] = vb.w;
        }
        __syncthreads();

#pragma unroll
        for (int kk = 0; kk < 16; kk++) {
            float4 a0 = *(const float4*)&As[kk][ty * 8];
            float4 a1 = *(const float4*)&As[kk][ty * 8 + 4];
            float4 b0 = *(const float4*)&Bs[kk][tx * 8];
            float4 b1 = *(const float4*)&Bs[kk][tx * 8 + 4];
            float a[8] = {a0.x, a0.y, a0.z, a0.w, a1.x, a1.y, a1.z, a1.w};
            float b[8] = {b0.x, b0.y, b0.z, b0.w, b1.x, b1.y, b1.z, b1.w};
#pragma unroll
            for (int i = 0; i < 8; i++)
#pragma unroll
                for (int j = 0; j < 8; j++) acc[i][j] += a[i] * b[j];
        }
        __syncthreads();
    }

    float bv[8];
#pragma unroll
    for (int j = 0; j < 8; j++) bv[j] = bias[n0 + tx * 8 + j];

    if (!HEADS) {
#pragma unroll
        for (int i = 0; i < 8; i++) {
            int m = m0 + ty * 8 + i;
            float4 r0 = make_float4(acc[i][0] + bv[0], acc[i][1] + bv[1],
                                    acc[i][2] + bv[2], acc[i][3] + bv[3]);
            float4 r1 = make_float4(acc[i][4] + bv[4], acc[i][5] + bv[5],
                                    acc[i][6] + bv[6], acc[i][7] + bv[7]);
            float* dst = Y + (size_t)m * D_ + n0 + tx * 8;
            *(float4*)(dst)     = r0;
            *(float4*)(dst + 4) = r1;
        }
    } else {
        const int n  = n0 + tx * 8;
        const int h  = n >> 6;
        const int hd = n & 63;         // 8 cols never cross a 64 boundary
#pragma unroll
        for (int i = 0; i < 8; i++) {
            int m  = m0 + ty * 8 + i;
            int bb = m >> 11;          // T_=2048
            int tt = m & (T_ - 1);
            float* dst = Y + (((size_t)(bb * H_ + h) * T_ + tt) * HD_ + hd);
            float4 r0 = make_float4(acc[i][0] + bv[0], acc[i][1] + bv[1],
                                    acc[i][2] + bv[2], acc[i][3] + bv[3]);
            float4 r1 = make_float4(acc[i][4] + bv[4], acc[i][5] + bv[5],
                                    acc[i][6] + bv[6], acc[i][7] + bv[7]);
            *(float4*)(dst)     = r0;
            *(float4*)(dst + 4) = r1;
        }
    }
}

// ---------------------------------------------------------------------------
// Causal flash attention, fp32. Block = (64 q-rows) x one (b,h).
// 256 threads: 16x16 grid, each thread owns 4 rows x 4 cols.
// Smem: q/k/p padded to stride 65 (kills worst bank conflicts), v stride 64.
// ---------------------------------------------------------------------------
#define ATT_SMEM_FLOATS (64*65 + 64*65 + 64*64 + 64*65 + 64*16 + 3*64)
#define ATT_SMEM_BYTES  (ATT_SMEM_FLOATS * 4)

__global__ __launch_bounds__(256, 2)
void attn_kernel(const float* __restrict__ gq,
                 const float* __restrict__ gk,
                 const float* __restrict__ gv,
                 float* __restrict__ go)
{
    extern __shared__ float sm[];
    float* q_s = sm;                 // [64][65]
    float* k_s = q_s + 64 * 65;      // [64][65]
    float* v_s = k_s + 64 * 65;      // [64][64]
    float* p_s = v_s + 64 * 64;      // [64][65]
    float* red = p_s + 64 * 65;      // [64][16]
    float* m_s = red + 64 * 16;      // [64]
    float* l_s = m_s + 64;           // [64]
    float* a_s = l_s + 64;           // [64]

    const int qi = blockIdx.x;       // q tile index (0..31)
    const int bh = blockIdx.y;       // b*H + h
    const int q0 = qi * 64;
    const int t  = threadIdx.x;
    const int cx = t & 15;
    const int ry = t >> 4;

    const float* qptr = gq + ((size_t)bh * T_ + q0) * HD_;

    // Load + scale Q tile (scale = 1/sqrt(64) = 0.125)
    for (int e = t; e < 64 * 64; e += 256) {
        int r = e >> 6, d = e & 63;
        q_s[r * 65 + d] = qptr[(size_t)r * HD_ + d] * 0.125f;
    }
    if (t < 64) { m_s[t] = -INFINITY; l_s[t] = 0.f; }

    float o[4][4];
#pragma unroll
    for (int i = 0; i < 4; i++)
#pragma unroll
        for (int j = 0; j < 4; j++) o[i][j] = 0.f;

    for (int jt = 0; jt <= qi; jt++) {
        const int k0 = jt * 64;
        __syncthreads();   // guard smem reuse (and q/m/l init on first iter)

        const float* kptr = gk + ((size_t)bh * T_ + k0) * HD_;
        const float* vptr = gv + ((size_t)bh * T_ + k0) * HD_;
        for (int e = t; e < 64 * 64; e += 256) {
            int r = e >> 6, d = e & 63;
            k_s[r * 65 + d] = kptr[e];
        }
        for (int f = t; f < 1024; f += 256) {
            int r = f >> 4, dq = (f & 15) << 2;
            *(float4*)(v_s + r * 64 + dq) = *(const float4*)(vptr + (size_t)r * 64 + dq);
        }
        __syncthreads();

        // S = Q K^T  (4x4 per thread)
        float s[4][4];
#pragma unroll
        for (int i = 0; i < 4; i++)
#pragma unroll
            for (int j = 0; j < 4; j++) s[i][j] = 0.f;

#pragma unroll 8
        for (int d = 0; d < 64; d++) {
            float a0 = q_s[(ry * 4 + 0) * 65 + d];
            float a1 = q_s[(ry * 4 + 1) * 65 + d];
            float a2 = q_s[(ry * 4 + 2) * 65 + d];
            float a3 = q_s[(ry * 4 + 3) * 65 + d];
            float b0 = k_s[(cx * 4 + 0) * 65 + d];
            float b1 = k_s[(cx * 4 + 1) * 65 + d];
            float b2 = k_s[(cx * 4 + 2) * 65 + d];
            float b3 = k_s[(cx * 4 + 3) * 65 + d];
            s[0][0] += a0 * b0; s[0][1] += a0 * b1; s[0][2] += a0 * b2; s[0][3] += a0 * b3;
            s[1][0] += a1 * b0; s[1][1] += a1 * b1; s[1][2] += a1 * b2; s[1][3] += a1 * b3;
            s[2][0] += a2 * b0; s[2][1] += a2 * b1; s[2][2] += a2 * b2; s[2][3] += a2 * b3;
            s[3][0] += a3 * b0; s[3][1] += a3 * b1; s[3][2] += a3 * b2; s[3][3] += a3 * b3;
        }

        if (jt == qi) {   // diagonal tile: causal mask (col > row -> -inf)
#pragma unroll
            for (int i = 0; i < 4; i++)
#pragma unroll
                for (int j = 0; j < 4; j++)
                    if (cx * 4 + j > ry * 4 + i) s[i][j] = -1e30f;
        }

        // Partial row max
#pragma unroll
        for (int i = 0; i < 4; i++) {
            float pm = fmaxf(fmaxf(s[i][0], s[i][1]), fmaxf(s[i][2], s[i][3]));
            red[(ry * 4 + i) * 16 + cx] = pm;
        }
        __syncthreads();

        if (t < 64) {
            float mo = m_s[t], mm = mo;
#pragma unroll
            for (int c = 0; c < 16; c++) mm = fmaxf(mm, red[t * 16 + c]);
            float al = __expf(mo - mm);
            m_s[t] = mm;
            a_s[t] = al;
            l_s[t] *= al;
        }
        __syncthreads();

        // P = exp(S - m), partial row sums, rescale O
#pragma unroll
        for (int i = 0; i < 4; i++) {
            float mi = m_s[ry * 4 + i];
            float al = a_s[ry * 4 + i];
            float rs = 0.f;
#pragma unroll
            for (int j = 0; j < 4; j++) {
                float p = __expf(s[i][j] - mi);
                p_s[(ry * 4 + i) * 65 + cx * 4 + j] = p;
                rs += p;
                o[i][j] *= al;
            }
            red[(ry * 4 + i) * 16 + cx] = rs;
        }
        __syncthreads();

        if (t < 64) {
            float ss = 0.f;
#pragma unroll
            for (int c = 0; c < 16; c++) ss += red[t * 16 + c];
            l_s[t] += ss;
        }

        // O += P V
#pragma unroll 8
        for (int kc = 0; kc < 64; kc++) {
            float a0 = p_s[(ry * 4 + 0) * 65 + kc];
            float a1 = p_s[(ry * 4 + 1) * 65 + kc];
            float a2 = p_s[(ry * 4 + 2) * 65 + kc];
            float a3 = p_s[(ry * 4 + 3) * 65 + kc];
            float b0 = v_s[kc * 64 + cx * 4 + 0];
            float b1 = v_s[kc * 64 + cx * 4 + 1];
            float b2 = v_s[kc * 64 + cx * 4 + 2];
            float b3 = v_s[kc * 64 + cx * 4 + 3];
            o[0][0] += a0 * b0; o[0][1] += a0 * b1; o[0][2] += a0 * b2; o[0][3] += a0 * b3;
            o[1][0] += a1 * b0; o[1][1] += a1 * b1; o[1][2] += a1 * b2; o[1][3] += a1 * b3;
            o[2][0] += a2 * b0; o[2][1] += a2 * b1; o[2][2] += a2 * b2; o[2][3] += a2 * b3;
            o[3][0] += a3 * b0; o[3][1] += a3 * b1; o[3][2] += a3 * b2; o[3][3] += a3 * b3;
        }
    }
    __syncthreads();

    // Normalize + write to [b*t, h*64+d] layout
    const int bb = bh >> 4;
    const int h  = bh & 15;
#pragma unroll
    for (int i = 0; i < 4; i++) {
        float inv = 1.0f / l_s[ry * 4 + i];
        int row = q0 + ry * 4 + i;
        float4 r = make_float4(o[i][0] * inv, o[i][1] * inv,
                               o[i][2] * inv, o[i][3] * inv);
        *(float4*)(go + ((size_t)(bb * T_ + row)) * D_ + h * 64 + cx * 4) = r;
    }
}

// ---------------------------------------------------------------------------
extern "C" void kernel_launch(void* const* d_in, const int* in_sizes, int n_in,
                              void* d_out, int out_size)
{
    (void)in_sizes; (void)n_in; (void)out_size;
    const float* Qin = (const float*)d_in[0];
    const float* Kin = (const float*)d_in[1];
    const float* Vin = (const float*)d_in[2];
    // d_in[3] = mask (causal, hardcoded)
    const float* Wq = (const float*)d_in[4];
    const float* bq = (const float*)d_in[5];
    const float* Wk = (const float*)d_in[6];
    const float* bk = (const float*)d_in[7];
    const float* Wv = (const float*)d_in[8];
    const float* bv = (const float*)d_in[9];
    const float* Wo = (const float*)d_in[10];
    const float* bo = (const float*)d_in[11];

    float *gq, *gk, *gv, *go;
    cudaGetSymbolAddress((void**)&gq, g_q);
    cudaGetSymbolAddress((void**)&gk, g_k);
    cudaGetSymbolAddress((void**)&gv, g_v);
    cudaGetSymbolAddress((void**)&go, g_o);

    dim3 gridG(D_ / 128, M_ / 128);   // (8, 64)
    gemm_bias_kernel<1><<<gridG, 256>>>(Qin, Wq, bq, gq);
    gemm_bias_kernel<1><<<gridG, 256>>>(Kin, Wk, bk, gk);
    gemm_bias_kernel<1><<<gridG, 256>>>(Vin, Wv, bv, gv);

    cudaFuncSetAttribute(attn_kernel,
                         cudaFuncAttributeMaxDynamicSharedMemorySize,
                         ATT_SMEM_BYTES);
    attn_kernel<<<dim3(T_ / 64, B_ * H_), 256, ATT_SMEM_BYTES>>>(gq, gk, gv, go);

    gemm_bias_kernel<0><<<gridG, 256>>>(go, Wo, bo, (float*)d_out);
}

// round 2
// speedup vs baseline: 2.7464x; 2.7464x over previous
#include <cuda_runtime.h>

#define B_  4
#define T_  2048
#define D_  1024
#define H_  16
#define HD_ 64
#define M_  (B_ * T_)

// Scratch (device globals — no allocations allowed)
__device__ float g_q[B_ * H_ * T_ * HD_];   // [b,h,t,hd]
__device__ float g_k[B_ * H_ * T_ * HD_];
__device__ float g_v[B_ * H_ * T_ * HD_];
__device__ float g_o[M_ * D_];              // attention output, [b*t, h*hd]

// ---------------------------------------------------------------------------
// helpers
// ---------------------------------------------------------------------------
__device__ __forceinline__ unsigned f2tf(float f) {
    unsigned u;
    asm("cvt.rna.tf32.f32 %0, %1;" : "=r"(u) : "f"(f));
    return u;
}

__device__ __forceinline__ void mma8(float* c, const unsigned* a, const unsigned* b) {
    asm volatile(
        "mma.sync.aligned.m16n8k8.row.col.f32.tf32.tf32.f32 "
        "{%0,%1,%2,%3},{%4,%5,%6,%7},{%8,%9},{%0,%1,%2,%3};"
        : "+f"(c[0]), "+f"(c[1]), "+f"(c[2]), "+f"(c[3])
        : "r"(a[0]), "r"(a[1]), "r"(a[2]), "r"(a[3]), "r"(b[0]), "r"(b[1]));
}

__device__ __forceinline__ void cp16(void* smem_dst, const void* gmem_src) {
    unsigned s = (unsigned)__cvta_generic_to_shared(smem_dst);
    asm volatile("cp.async.cg.shared.global [%0], [%1], 16;\n" :: "r"(s), "l"(gmem_src));
}
#define CP_COMMIT()  asm volatile("cp.async.commit_group;\n" ::: "memory")
#define CP_WAIT(n)   asm volatile("cp.async.wait_group %0;\n" :: "n"(n) : "memory")

// ---------------------------------------------------------------------------
// GEMM: Y = X[M,1024] @ W[N,1024]^T + bias, tf32 mma, 128x128x32 tiles.
// 256 threads = 8 warps in 2x4; warp tile 64x32 (4 m16 x 4 n8 mma tiles).
// Double-buffered cp.async. HEADS=1 scatters into [b,h,t,hd].
// ---------------------------------------------------------------------------
#define GS_A(buf, r, k) smg[(buf) * 4608 + (r) * 36 + (k)]
#define GS_B(buf, r, k) smg[9216 + (buf) * 4608 + (r) * 36 + (k)]
#define GEMM_SMEM_BYTES (18432 * 4)   // 2 arrays * 2 bufs * 128*36 floats

template <int HEADS>
__global__ __launch_bounds__(256)
void gemm_mma(const float* __restrict__ X,
              const float* __restrict__ W,
              const float* __restrict__ bias,
              float* __restrict__ Y)
{
    extern __shared__ float smg[];
    const int m0 = blockIdx.y * 128, n0 = blockIdx.x * 128;
    const int t = threadIdx.x, wid = t >> 5, lane = t & 31;
    const int wm = wid >> 2, wn = wid & 3;   // 2 x 4 warps
    const int lr = lane >> 2, lc = lane & 3;

    float acc[4][4][4];
#pragma unroll
    for (int mt = 0; mt < 4; mt++)
#pragma unroll
        for (int nt = 0; nt < 4; nt++)
#pragma unroll
            for (int e = 0; e < 4; e++) acc[mt][nt][e] = 0.f;

    // chunk loader: 128x32 of A and B each
#define LOAD_CHUNK(buf, k0)                                                   \
    {                                                                         \
        _Pragma("unroll")                                                     \
        for (int i = 0; i < 4; i++) {                                         \
            int idx = t + i * 256;                                            \
            int r = idx >> 3, kq = (idx & 7) << 2;                            \
            cp16(&GS_A(buf, r, kq), X + (size_t)(m0 + r) * D_ + (k0) + kq);   \
            cp16(&GS_B(buf, r, kq), W + (size_t)(n0 + r) * D_ + (k0) + kq);   \
        }                                                                     \
        CP_COMMIT();                                                          \
    }

    LOAD_CHUNK(0, 0);

    for (int c = 0; c < 32; c++) {
        const int buf = c & 1;
        if (c < 31) { LOAD_CHUNK(buf ^ 1, (c + 1) * 32); CP_WAIT(1); }
        else        { CP_WAIT(0); }
        __syncthreads();

#pragma unroll
        for (int k8 = 0; k8 < 32; k8 += 8) {
            unsigned a[4][4], b[4][2];
#pragma unroll
            for (int mt = 0; mt < 4; mt++) {
                int row = wm * 64 + mt * 16 + lr;
                a[mt][0] = f2tf(GS_A(buf, row,     k8 + lc));
                a[mt][1] = f2tf(GS_A(buf, row + 8, k8 + lc));
                a[mt][2] = f2tf(GS_A(buf, row,     k8 + lc + 4));
                a[mt][3] = f2tf(GS_A(buf, row + 8, k8 + lc + 4));
            }
#pragma unroll
            for (int nt = 0; nt < 4; nt++) {
                int col = wn * 32 + nt * 8 + lr;
                b[nt][0] = f2tf(GS_B(buf, col, k8 + lc));
                b[nt][1] = f2tf(GS_B(buf, col, k8 + lc + 4));
            }
#pragma unroll
            for (int mt = 0; mt < 4; mt++)
#pragma unroll
                for (int nt = 0; nt < 4; nt++)
                    mma8(acc[mt][nt], a[mt], b[nt]);
        }
        __syncthreads();
    }

    // epilogue
    float bv[4][2];
#pragma unroll
    for (int nt = 0; nt < 4; nt++) {
        int col = n0 + wn * 32 + nt * 8 + 2 * lc;
        bv[nt][0] = bias[col];
        bv[nt][1] = bias[col + 1];
    }

#pragma unroll
    for (int mt = 0; mt < 4; mt++) {
#pragma unroll
        for (int nt = 0; nt < 4; nt++) {
            int row = m0 + wm * 64 + mt * 16 + lr;
            int col = n0 + wn * 32 + nt * 8 + 2 * lc;
            float2 v0 = make_float2(acc[mt][nt][0] + bv[nt][0],
                                    acc[mt][nt][1] + bv[nt][1]);
            float2 v1 = make_float2(acc[mt][nt][2] + bv[nt][0],
                                    acc[mt][nt][3] + bv[nt][1]);
            if (!HEADS) {
                *(float2*)(Y + (size_t)row * D_ + col)       = v0;
                *(float2*)(Y + (size_t)(row + 8) * D_ + col) = v1;
            } else {
                int h = col >> 6, hd = col & 63;
                int bb0 = row >> 11,       tt0 = row & (T_ - 1);
                int bb1 = (row + 8) >> 11, tt1 = (row + 8) & (T_ - 1);
                *(float2*)(Y + (((size_t)(bb0 * H_ + h) * T_ + tt0) * HD_ + hd)) = v0;
                *(float2*)(Y + (((size_t)(bb1 * H_ + h) * T_ + tt1) * HD_ + hd)) = v1;
            }
        }
    }
#undef LOAD_CHUNK
}

// ---------------------------------------------------------------------------
// Causal flash attention with tf32 mma.
// Block: 64 q-rows x one (b,h). 256 threads = 8 warps in 2x4;
// warp tile 32x16 (2 m16 x 2 n8). S and PV via mma, softmax SIMT in smem.
// ---------------------------------------------------------------------------
#define ATT_SMEM_FLOATS (4 * 64 * 68 + 256 + 3 * 64)
#define ATT_SMEM_BYTES  (ATT_SMEM_FLOATS * 4)

__global__ __launch_bounds__(256)
void attn_mma(const float* __restrict__ gq,
              const float* __restrict__ gk,
              const float* __restrict__ gv,
              float* __restrict__ go)
{
    extern __shared__ float sm[];
    float* q_s = sm;                 // [64][68] (Q, pre-scaled)
    float* k_s = q_s + 64 * 68;      // [64][68]
    float* v_s = k_s + 64 * 68;      // [64][68]
    float* p_s = v_s + 64 * 68;      // [64][68] (S, then P)
    float* red = p_s + 64 * 68;      // [4][64]
    float* m_s = red + 256;          // [64]
    float* l_s = m_s + 64;           // [64]
    float* a_s = l_s + 64;           // [64]

    const int qi = blockIdx.x, bh = blockIdx.y, q0 = qi * 64;
    const int t = threadIdx.x, wid = t >> 5, lane = t & 31;
    const int wm = wid >> 2, wn = wid & 3;   // 2 x 4
    const int lr = lane >> 2, lc = lane & 3;
    const int sr = t >> 2, sseg = t & 3;     // softmax mapping: row, 16-col segment

    const float* qptr = gq + ((size_t)bh * T_ + q0) * HD_;
    for (int e = t; e < 64 * 64; e += 256) {
        int r = e >> 6, d = e & 63;
        q_s[r * 68 + d] = qptr[e] * 0.125f;
    }
    if (t < 64) { m_s[t] = -INFINITY; l_s[t] = 0.f; }

    float o[2][2][4];
#pragma unroll
    for (int mt = 0; mt < 2; mt++)
#pragma unroll
        for (int nt = 0; nt < 2; nt++)
#pragma unroll
            for (int e = 0; e < 4; e++) o[mt][nt][e] = 0.f;

    for (int jt = 0; jt <= qi; jt++) {
        __syncthreads();   // guard k_s/v_s reuse (and q/m/l init first iter)

        const float* kptr = gk + ((size_t)bh * T_ + jt * 64) * HD_;
        const float* vptr = gv + ((size_t)bh * T_ + jt * 64) * HD_;
        for (int f = t; f < 1024; f += 256) {
            int r = f >> 4, dq = (f & 15) << 2;
            *(float4*)(k_s + r * 68 + dq) = *(const float4*)(kptr + (size_t)r * 64 + dq);
            *(float4*)(v_s + r * 68 + dq) = *(const float4*)(vptr + (size_t)r * 64 + dq);
        }
        __syncthreads();

        // ---- S = Q K^T ----
        float s[2][2][4];
#pragma unroll
        for (int mt = 0; mt < 2; mt++)
#pragma unroll
            for (int nt = 0; nt < 2; nt++)
#pragma unroll
                for (int e = 0; e < 4; e++) s[mt][nt][e] = 0.f;

#pragma unroll
        for (int k8 = 0; k8 < 64; k8 += 8) {
            unsigned a[2][4], b[2][2];
#pragma unroll
            for (int mt = 0; mt < 2; mt++) {
                int row = wm * 32 + mt * 16 + lr;
                a[mt][0] = f2tf(q_s[row * 68 + k8 + lc]);
                a[mt][1] = f2tf(q_s[(row + 8) * 68 + k8 + lc]);
                a[mt][2] = f2tf(q_s[row * 68 + k8 + lc + 4]);
                a[mt][3] = f2tf(q_s[(row + 8) * 68 + k8 + lc + 4]);
            }
#pragma unroll
            for (int nt = 0; nt < 2; nt++) {
                int col = wn * 16 + nt * 8 + lr;
                b[nt][0] = f2tf(k_s[col * 68 + k8 + lc]);
                b[nt][1] = f2tf(k_s[col * 68 + k8 + lc + 4]);
            }
#pragma unroll
            for (int mt = 0; mt < 2; mt++)
#pragma unroll
                for (int nt = 0; nt < 2; nt++)
                    mma8(s[mt][nt], a[mt], b[nt]);
        }

        // mask (diagonal tile) + store S to smem
#pragma unroll
        for (int mt = 0; mt < 2; mt++) {
#pragma unroll
            for (int nt = 0; nt < 2; nt++) {
                int row0 = wm * 32 + mt * 16 + lr;
                int col0 = wn * 16 + nt * 8 + 2 * lc;
                if (jt == qi) {
                    if (col0     > row0)     s[mt][nt][0] = -1e30f;
                    if (col0 + 1 > row0)     s[mt][nt][1] = -1e30f;
                    if (col0     > row0 + 8) s[mt][nt][2] = -1e30f;
                    if (col0 + 1 > row0 + 8) s[mt][nt][3] = -1e30f;
                }
                p_s[row0 * 68 + col0]           = s[mt][nt][0];
                p_s[row0 * 68 + col0 + 1]       = s[mt][nt][1];
                p_s[(row0 + 8) * 68 + col0]     = s[mt][nt][2];
                p_s[(row0 + 8) * 68 + col0 + 1] = s[mt][nt][3];
            }
        }
        __syncthreads();

        // ---- softmax: partial row max ----
        {
            const float* pr = p_s + sr * 68 + sseg * 16;
            float mx = pr[0];
#pragma unroll
            for (int j = 1; j < 16; j++) mx = fmaxf(mx, pr[j]);
            red[sseg * 64 + sr] = mx;
        }
        __syncthreads();
        if (t < 64) {
            float mo = m_s[t];
            float mm = fmaxf(fmaxf(red[t], red[64 + t]), fmaxf(red[128 + t], red[192 + t]));
            mm = fmaxf(mm, mo);
            float al = __expf(mo - mm);
            m_s[t] = mm; a_s[t] = al; l_s[t] *= al;
        }
        __syncthreads();

        // ---- exp + partial sums ----
        {
            float mi = m_s[sr];
            float* pr = p_s + sr * 68 + sseg * 16;
            float ssum = 0.f;
#pragma unroll
            for (int j = 0; j < 16; j++) {
                float p = __expf(pr[j] - mi);
                pr[j] = p;
                ssum += p;
            }
            red[sseg * 64 + sr] = ssum;
        }
        // rescale O fragments by alpha (a_s valid since last sync)
#pragma unroll
        for (int mt = 0; mt < 2; mt++) {
            float al0 = a_s[wm * 32 + mt * 16 + lr];
            float al1 = a_s[wm * 32 + mt * 16 + lr + 8];
#pragma unroll
            for (int nt = 0; nt < 2; nt++) {
                o[mt][nt][0] *= al0; o[mt][nt][1] *= al0;
                o[mt][nt][2] *= al1; o[mt][nt][3] *= al1;
            }
        }
        __syncthreads();
        if (t < 64)
            l_s[t] += red[t] + red[64 + t] + red[128 + t] + red[192 + t];

        // ---- O += P V ----
#pragma unroll
        for (int k8 = 0; k8 < 64; k8 += 8) {
            unsigned a[2][4], b[2][2];
#pragma unroll
            for (int mt = 0; mt < 2; mt++) {
                int row = wm * 32 + mt * 16 + lr;
                a[mt][0] = f2tf(p_s[row * 68 + k8 + lc]);
                a[mt][1] = f2tf(p_s[(row + 8) * 68 + k8 + lc]);
                a[mt][2] = f2tf(p_s[row * 68 + k8 + lc + 4]);
                a[mt][3] = f2tf(p_s[(row + 8) * 68 + k8 + lc + 4]);
            }
#pragma unroll
            for (int nt = 0; nt < 2; nt++) {
                int col = wn * 16 + nt * 8 + lr;
                b[nt][0] = f2tf(v_s[(k8 + lc) * 68 + col]);
                b[nt][1] = f2tf(v_s[(k8 + lc + 4) * 68 + col]);
            }
#pragma unroll
            for (int mt = 0; mt < 2; mt++)
#pragma unroll
                for (int nt = 0; nt < 2; nt++)
                    mma8(o[mt][nt], a[mt], b[nt]);
        }
    }
    __syncthreads();

    // epilogue: normalize + write [b*t, h*64 + d]
    const int bb = bh >> 4, h = bh & 15;
#pragma unroll
    for (int mt = 0; mt < 2; mt++) {
        int lrow0 = wm * 32 + mt * 16 + lr;
        float inv0 = 1.0f / l_s[lrow0];
        float inv1 = 1.0f / l_s[lrow0 + 8];
#pragma unroll
        for (int nt = 0; nt < 2; nt++) {
            int col = wn * 16 + nt * 8 + 2 * lc;
            int grow0 = q0 + lrow0;
            float2 v0 = make_float2(o[mt][nt][0] * inv0, o[mt][nt][1] * inv0);
            float2 v1 = make_float2(o[mt][nt][2] * inv1, o[mt][nt][3] * inv1);
            *(float2*)(go + ((size_t)(bb * T_ + grow0)) * D_ + h * 64 + col)       = v0;
            *(float2*)(go + ((size_t)(bb * T_ + grow0 + 8)) * D_ + h * 64 + col)   = v1;
        }
    }
}

// ---------------------------------------------------------------------------
extern "C" void kernel_launch(void* const* d_in, const int* in_sizes, int n_in,
                              void* d_out, int out_size)
{
    (void)in_sizes; (void)n_in; (void)out_size;
    const float* Qin = (const float*)d_in[0];
    const float* Kin = (const float*)d_in[1];
    const float* Vin = (const float*)d_in[2];
    // d_in[3] = mask (causal, hardcoded)
    const float* Wq = (const float*)d_in[4];
    const float* bq = (const float*)d_in[5];
    const float* Wk = (const float*)d_in[6];
    const float* bk = (const float*)d_in[7];
    const float* Wv = (const float*)d_in[8];
    const float* bv = (const float*)d_in[9];
    const float* Wo = (const float*)d_in[10];
    const float* bo = (const float*)d_in[11];

    float *gq, *gk, *gv, *go;
    cudaGetSymbolAddress((void**)&gq, g_q);
    cudaGetSymbolAddress((void**)&gk, g_k);
    cudaGetSymbolAddress((void**)&gv, g_v);
    cudaGetSymbolAddress((void**)&go, g_o);

    cudaFuncSetAttribute(gemm_mma<1>, cudaFuncAttributeMaxDynamicSharedMemorySize, GEMM_SMEM_BYTES);
    cudaFuncSetAttribute(gemm_mma<0>, cudaFuncAttributeMaxDynamicSharedMemorySize, GEMM_SMEM_BYTES);
    cudaFuncSetAttribute(attn_mma,    cudaFuncAttributeMaxDynamicSharedMemorySize, ATT_SMEM_BYTES);

    dim3 gridG(D_ / 128, M_ / 128);   // (8, 64)
    gemm_mma<1><<<gridG, 256, GEMM_SMEM_BYTES>>>(Qin, Wq, bq, gq);
    gemm_mma<1><<<gridG, 256, GEMM_SMEM_BYTES>>>(Kin, Wk, bk, gk);
    gemm_mma<1><<<gridG, 256, GEMM_SMEM_BYTES>>>(Vin, Wv, bv, gv);

    attn_mma<<<dim3(T_ / 64, B_ * H_), 256, ATT_SMEM_BYTES>>>(gq, gk, gv, go);

    gemm_mma<0><<<gridG, 256, GEMM_SMEM_BYTES>>>(go, Wo, bo, (float*)d_out);
}

// round 3
// speedup vs baseline: 3.3428x; 1.2171x over previous
#include <cuda_runtime.h>

#define B_  4
#define T_  2048
#define D_  1024
#define H_  16
#define HD_ 64
#define M_  (B_ * T_)

// Scratch (device globals — no allocations allowed)
__device__ float g_q[B_ * H_ * T_ * HD_];   // [b,h,t,hd]
__device__ float g_k[B_ * H_ * T_ * HD_];
__device__ float g_v[B_ * H_ * T_ * HD_];
__device__ float g_o[M_ * D_];              // attention output, [b*t, h*hd]

// ---------------------------------------------------------------------------
// helpers
// ---------------------------------------------------------------------------
__device__ __forceinline__ unsigned f2tf(float f) {
    unsigned u;
    asm("cvt.rna.tf32.f32 %0, %1;" : "=r"(u) : "f"(f));
    return u;
}

__device__ __forceinline__ void mma8(float* c, const unsigned* a, const unsigned* b) {
    asm volatile(
        "mma.sync.aligned.m16n8k8.row.col.f32.tf32.tf32.f32 "
        "{%0,%1,%2,%3},{%4,%5,%6,%7},{%8,%9},{%0,%1,%2,%3};"
        : "+f"(c[0]), "+f"(c[1]), "+f"(c[2]), "+f"(c[3])
        : "r"(a[0]), "r"(a[1]), "r"(a[2]), "r"(a[3]), "r"(b[0]), "r"(b[1]));
}

__device__ __forceinline__ void cp16(void* smem_dst, const void* gmem_src) {
    unsigned s = (unsigned)__cvta_generic_to_shared(smem_dst);
    asm volatile("cp.async.cg.shared.global [%0], [%1], 16;\n" :: "r"(s), "l"(gmem_src));
}
#define CP_COMMIT()  asm volatile("cp.async.commit_group;\n" ::: "memory")
#define CP_WAIT(n)   asm volatile("cp.async.wait_group %0;\n" :: "n"(n) : "memory")

// ---------------------------------------------------------------------------
// GEMM: Y = X[M,1024] @ W[N,1024]^T + bias, tf32 mma, 128x128x32 tiles.
// (unchanged from round 2 — proven correct)
// ---------------------------------------------------------------------------
#define GS_A(buf, r, k) smg[(buf) * 4608 + (r) * 36 + (k)]
#define GS_B(buf, r, k) smg[9216 + (buf) * 4608 + (r) * 36 + (k)]
#define GEMM_SMEM_BYTES (18432 * 4)

template <int HEADS>
__global__ __launch_bounds__(256)
void gemm_mma(const float* __restrict__ X,
              const float* __restrict__ W,
              const float* __restrict__ bias,
              float* __restrict__ Y)
{
    extern __shared__ float smg[];
    const int m0 = blockIdx.y * 128, n0 = blockIdx.x * 128;
    const int t = threadIdx.x, wid = t >> 5, lane = t & 31;
    const int wm = wid >> 2, wn = wid & 3;
    const int lr = lane >> 2, lc = lane & 3;

    float acc[4][4][4];
#pragma unroll
    for (int mt = 0; mt < 4; mt++)
#pragma unroll
        for (int nt = 0; nt < 4; nt++)
#pragma unroll
            for (int e = 0; e < 4; e++) acc[mt][nt][e] = 0.f;

#define LOAD_CHUNK(buf, k0)                                                   \
    {                                                                         \
        _Pragma("unroll")                                                     \
        for (int i = 0; i < 4; i++) {                                         \
            int idx = t + i * 256;                                            \
            int r = idx >> 3, kq = (idx & 7) << 2;                            \
            cp16(&GS_A(buf, r, kq), X + (size_t)(m0 + r) * D_ + (k0) + kq);   \
            cp16(&GS_B(buf, r, kq), W + (size_t)(n0 + r) * D_ + (k0) + kq);   \
        }                                                                     \
        CP_COMMIT();                                                          \
    }

    LOAD_CHUNK(0, 0);

    for (int c = 0; c < 32; c++) {
        const int buf = c & 1;
        if (c < 31) { LOAD_CHUNK(buf ^ 1, (c + 1) * 32); CP_WAIT(1); }
        else        { CP_WAIT(0); }
        __syncthreads();

#pragma unroll
        for (int k8 = 0; k8 < 32; k8 += 8) {
            unsigned a[4][4], b[4][2];
#pragma unroll
            for (int mt = 0; mt < 4; mt++) {
                int row = wm * 64 + mt * 16 + lr;
                a[mt][0] = f2tf(GS_A(buf, row,     k8 + lc));
                a[mt][1] = f2tf(GS_A(buf, row + 8, k8 + lc));
                a[mt][2] = f2tf(GS_A(buf, row,     k8 + lc + 4));
                a[mt][3] = f2tf(GS_A(buf, row + 8, k8 + lc + 4));
            }
#pragma unroll
            for (int nt = 0; nt < 4; nt++) {
                int col = wn * 32 + nt * 8 + lr;
                b[nt][0] = f2tf(GS_B(buf, col, k8 + lc));
                b[nt][1] = f2tf(GS_B(buf, col, k8 + lc + 4));
            }
#pragma unroll
            for (int mt = 0; mt < 4; mt++)
#pragma unroll
                for (int nt = 0; nt < 4; nt++)
                    mma8(acc[mt][nt], a[mt], b[nt]);
        }
        __syncthreads();
    }

    float bv[4][2];
#pragma unroll
    for (int nt = 0; nt < 4; nt++) {
        int col = n0 + wn * 32 + nt * 8 + 2 * lc;
        bv[nt][0] = bias[col];
        bv[nt][1] = bias[col + 1];
    }

#pragma unroll
    for (int mt = 0; mt < 4; mt++) {
#pragma unroll
        for (int nt = 0; nt < 4; nt++) {
            int row = m0 + wm * 64 + mt * 16 + lr;
            int col = n0 + wn * 32 + nt * 8 + 2 * lc;
            float2 v0 = make_float2(acc[mt][nt][0] + bv[nt][0],
                                    acc[mt][nt][1] + bv[nt][1]);
            float2 v1 = make_float2(acc[mt][nt][2] + bv[nt][0],
                                    acc[mt][nt][3] + bv[nt][1]);
            if (!HEADS) {
                *(float2*)(Y + (size_t)row * D_ + col)       = v0;
                *(float2*)(Y + (size_t)(row + 8) * D_ + col) = v1;
            } else {
                int h = col >> 6, hd = col & 63;
                int bb0 = row >> 11,       tt0 = row & (T_ - 1);
                int bb1 = (row + 8) >> 11, tt1 = (row + 8) & (T_ - 1);
                *(float2*)(Y + (((size_t)(bb0 * H_ + h) * T_ + tt0) * HD_ + hd)) = v0;
                *(float2*)(Y + (((size_t)(bb1 * H_ + h) * T_ + tt1) * HD_ + hd)) = v1;
            }
        }
    }
#undef LOAD_CHUNK
}

// ---------------------------------------------------------------------------
// Causal flash attention, register-resident softmax.
// Block: 128 q-rows x one (b,h). 8 warps; warp = 16 q-rows x full 64 KV cols.
// Q fragments in registers (loaded once). S/P in registers; softmax via
// quad shuffles. P->A fragment layout via shuffles. K/V cp.async dbl-buffered.
// K smem stride 68 (conflict-free for its read pattern), V stride 72.
// ---------------------------------------------------------------------------
#define ATT2_K_STRIDE 68
#define ATT2_V_STRIDE 72
#define ATT2_SMEM_FLOATS (2 * 64 * ATT2_K_STRIDE + 2 * 64 * ATT2_V_STRIDE)
#define ATT2_SMEM_BYTES  (ATT2_SMEM_FLOATS * 4)

__global__ __launch_bounds__(256)
void attn_mma2(const float* __restrict__ gq,
               const float* __restrict__ gk,
               const float* __restrict__ gv,
               float* __restrict__ go)
{
    extern __shared__ float sm[];
    float* ksm = sm;                        // [2][64][68]
    float* vsm = sm + 2 * 64 * ATT2_K_STRIDE; // [2][64][72]

    const int bh = blockIdx.x;              // b*H + h
    const int qi = blockIdx.y;              // q tile (128 rows)
    const int q0 = qi * 128;
    const int t = threadIdx.x, w = t >> 5, lane = t & 31;
    const int lr = lane >> 2, lc = lane & 3;
    const int row0 = w * 16 + lr;           // local q row (0..127), +8 for second

    const float* qptr = gq + ((size_t)bh * T_ + q0) * HD_;
    const float* kbase = gk + (size_t)bh * T_ * HD_;
    const float* vbase = gv + (size_t)bh * T_ * HD_;

    // Q fragments in registers, pre-scaled by 1/sqrt(64)
    unsigned qa[8][4];
#pragma unroll
    for (int c = 0; c < 8; c++) {
        qa[c][0] = f2tf(qptr[(size_t)row0 * HD_ + c * 8 + lc] * 0.125f);
        qa[c][1] = f2tf(qptr[(size_t)(row0 + 8) * HD_ + c * 8 + lc] * 0.125f);
        qa[c][2] = f2tf(qptr[(size_t)row0 * HD_ + c * 8 + lc + 4] * 0.125f);
        qa[c][3] = f2tf(qptr[(size_t)(row0 + 8) * HD_ + c * 8 + lc + 4] * 0.125f);
    }

    float o[8][4];
#pragma unroll
    for (int nt = 0; nt < 8; nt++)
#pragma unroll
        for (int e = 0; e < 4; e++) o[nt][e] = 0.f;
    float mr0 = -INFINITY, mr1 = -INFINITY, l0 = 0.f, l1 = 0.f;

    const int n_tiles = 2 * qi + 2;

#define LOADKV(jt, buf)                                                        \
    {                                                                          \
        const float* kp = kbase + (size_t)(jt) * 64 * HD_;                     \
        const float* vp = vbase + (size_t)(jt) * 64 * HD_;                     \
        float* kd = ksm + (buf) * 64 * ATT2_K_STRIDE;                          \
        float* vd = vsm + (buf) * 64 * ATT2_V_STRIDE;                          \
        _Pragma("unroll")                                                      \
        for (int i = 0; i < 4; i++) {                                          \
            int f = t + i * 256;                                               \
            int r = f >> 4, c4 = (f & 15) << 2;                                \
            cp16(kd + r * ATT2_K_STRIDE + c4, kp + (size_t)r * HD_ + c4);      \
            cp16(vd + r * ATT2_V_STRIDE + c4, vp + (size_t)r * HD_ + c4);      \
        }                                                                      \
        CP_COMMIT();                                                           \
    }

    LOADKV(0, 0);

    const int srcA = (lane & ~3) + (lc >> 1);
    const int srcB = srcA + 2;

    for (int jt = 0; jt < n_tiles; jt++) {
        CP_WAIT(0);
        __syncthreads();
        if (jt + 1 < n_tiles) LOADKV(jt + 1, (jt + 1) & 1);

        const int buf = jt & 1;
        const int k0 = jt * 64;
        const float* kb = ksm + buf * 64 * ATT2_K_STRIDE;
        const float* vb = vsm + buf * 64 * ATT2_V_STRIDE;

        // warp fully masked by this tile? (all its rows < k0)
        if (k0 > q0 + w * 16 + 15) continue;

        // ---- S = Q K^T ----
        float s[8][4];
#pragma unroll
        for (int nt = 0; nt < 8; nt++)
#pragma unroll
            for (int e = 0; e < 4; e++) s[nt][e] = 0.f;

#pragma unroll
        for (int c = 0; c < 8; c++) {
#pragma unroll
            for (int nt = 0; nt < 8; nt++) {
                unsigned b[2];
                b[0] = f2tf(kb[(nt * 8 + lr) * ATT2_K_STRIDE + c * 8 + lc]);
                b[1] = f2tf(kb[(nt * 8 + lr) * ATT2_K_STRIDE + c * 8 + lc + 4]);
                mma8(s[nt], qa[c], b);
            }
        }

        // ---- causal mask (last two tiles only) ----
        if (jt >= 2 * qi) {
            const int rg0 = q0 + row0, rg1 = rg0 + 8;
#pragma unroll
            for (int nt = 0; nt < 8; nt++) {
                int cg = k0 + nt * 8 + 2 * lc;
                if (cg     > rg0) s[nt][0] = -1e30f;
                if (cg + 1 > rg0) s[nt][1] = -1e30f;
                if (cg     > rg1) s[nt][2] = -1e30f;
                if (cg + 1 > rg1) s[nt][3] = -1e30f;
            }
        }

        // ---- online softmax in registers ----
        float rm0 = -INFINITY, rm1 = -INFINITY;
#pragma unroll
        for (int nt = 0; nt < 8; nt++) {
            rm0 = fmaxf(rm0, fmaxf(s[nt][0], s[nt][1]));
            rm1 = fmaxf(rm1, fmaxf(s[nt][2], s[nt][3]));
        }
        rm0 = fmaxf(rm0, __shfl_xor_sync(0xffffffffu, rm0, 1));
        rm0 = fmaxf(rm0, __shfl_xor_sync(0xffffffffu, rm0, 2));
        rm1 = fmaxf(rm1, __shfl_xor_sync(0xffffffffu, rm1, 1));
        rm1 = fmaxf(rm1, __shfl_xor_sync(0xffffffffu, rm1, 2));

        float mn0 = fmaxf(mr0, rm0), mn1 = fmaxf(mr1, rm1);
        float al0 = __expf(mr0 - mn0), al1 = __expf(mr1 - mn1);
        mr0 = mn0; mr1 = mn1;

        unsigned u[8][4];
        float rs0 = 0.f, rs1 = 0.f;
#pragma unroll
        for (int nt = 0; nt < 8; nt++) {
            float p0 = __expf(s[nt][0] - mn0);
            float p1 = __expf(s[nt][1] - mn0);
            float p2 = __expf(s[nt][2] - mn1);
            float p3 = __expf(s[nt][3] - mn1);
            rs0 += p0 + p1; rs1 += p2 + p3;
            u[nt][0] = f2tf(p0); u[nt][1] = f2tf(p1);
            u[nt][2] = f2tf(p2); u[nt][3] = f2tf(p3);
        }
        rs0 += __shfl_xor_sync(0xffffffffu, rs0, 1);
        rs0 += __shfl_xor_sync(0xffffffffu, rs0, 2);
        rs1 += __shfl_xor_sync(0xffffffffu, rs1, 1);
        rs1 += __shfl_xor_sync(0xffffffffu, rs1, 2);

        l0 = l0 * al0 + rs0;
        l1 = l1 * al1 + rs1;
#pragma unroll
        for (int nt = 0; nt < 8; nt++) {
            o[nt][0] *= al0; o[nt][1] *= al0;
            o[nt][2] *= al1; o[nt][3] *= al1;
        }

        // ---- O += P V  (P: C-layout -> A-layout via quad shuffles) ----
#pragma unroll
        for (int c = 0; c < 8; c++) {
            unsigned a[4], x0, x1;
            x0 = __shfl_sync(0xffffffffu, u[c][0], srcA);
            x1 = __shfl_sync(0xffffffffu, u[c][1], srcA);
            a[0] = (lc & 1) ? x1 : x0;
            x0 = __shfl_sync(0xffffffffu, u[c][2], srcA);
            x1 = __shfl_sync(0xffffffffu, u[c][3], srcA);
            a[1] = (lc & 1) ? x1 : x0;
            x0 = __shfl_sync(0xffffffffu, u[c][0], srcB);
            x1 = __shfl_sync(0xffffffffu, u[c][1], srcB);
            a[2] = (lc & 1) ? x1 : x0;
            x0 = __shfl_sync(0xffffffffu, u[c][2], srcB);
            x1 = __shfl_sync(0xffffffffu, u[c][3], srcB);
            a[3] = (lc & 1) ? x1 : x0;

#pragma unroll
            for (int nt = 0; nt < 8; nt++) {
                unsigned b[2];
                b[0] = f2tf(vb[(c * 8 + lc) * ATT2_V_STRIDE + nt * 8 + lr]);
                b[1] = f2tf(vb[(c * 8 + lc + 4) * ATT2_V_STRIDE + nt * 8 + lr]);
                mma8(o[nt], a, b);
            }
        }
    }
#undef LOADKV

    // ---- epilogue: normalize + write [b*t, h*64 + d] ----
    const int bb = bh >> 4, h = bh & 15;
    const float inv0 = 1.0f / l0, inv1 = 1.0f / l1;
    const int grow0 = q0 + row0;
#pragma unroll
    for (int nt = 0; nt < 8; nt++) {
        int col = h * 64 + nt * 8 + 2 * lc;
        float2 v0 = make_float2(o[nt][0] * inv0, o[nt][1] * inv0);
        float2 v1 = make_float2(o[nt][2] * inv1, o[nt][3] * inv1);
        *(float2*)(go + (size_t)(bb * T_ + grow0) * D_ + col)     = v0;
        *(float2*)(go + (size_t)(bb * T_ + grow0 + 8) * D_ + col) = v1;
    }
}

// ---------------------------------------------------------------------------
extern "C" void kernel_launch(void* const* d_in, const int* in_sizes, int n_in,
                              void* d_out, int out_size)
{
    (void)in_sizes; (void)n_in; (void)out_size;
    const float* Qin = (const float*)d_in[0];
    const float* Kin = (const float*)d_in[1];
    const float* Vin = (const float*)d_in[2];
    // d_in[3] = mask (causal, hardcoded)
    const float* Wq = (const float*)d_in[4];
    const float* bq = (const float*)d_in[5];
    const float* Wk = (const float*)d_in[6];
    const float* bk = (const float*)d_in[7];
    const float* Wv = (const float*)d_in[8];
    const float* bv = (const float*)d_in[9];
    const float* Wo = (const float*)d_in[10];
    const float* bo = (const float*)d_in[11];

    float *gq, *gk, *gv, *go;
    cudaGetSymbolAddress((void**)&gq, g_q);
    cudaGetSymbolAddress((void**)&gk, g_k);
    cudaGetSymbolAddress((void**)&gv, g_v);
    cudaGetSymbolAddress((void**)&go, g_o);

    cudaFuncSetAttribute(gemm_mma<1>, cudaFuncAttributeMaxDynamicSharedMemorySize, GEMM_SMEM_BYTES);
    cudaFuncSetAttribute(gemm_mma<0>, cudaFuncAttributeMaxDynamicSharedMemorySize, GEMM_SMEM_BYTES);
    cudaFuncSetAttribute(attn_mma2,   cudaFuncAttributeMaxDynamicSharedMemorySize, ATT2_SMEM_BYTES);

    dim3 gridG(D_ / 128, M_ / 128);   // (8, 64)
    gemm_mma<1><<<gridG, 256, GEMM_SMEM_BYTES>>>(Qin, Wq, bq, gq);
    gemm_mma<1><<<gridG, 256, GEMM_SMEM_BYTES>>>(Kin, Wk, bk, gk);
    gemm_mma<1><<<gridG, 256, GEMM_SMEM_BYTES>>>(Vin, Wv, bv, gv);

    attn_mma2<<<dim3(B_ * H_, T_ / 128), 256, ATT2_SMEM_BYTES>>>(gq, gk, gv, go);

    gemm_mma<0><<<gridG, 256, GEMM_SMEM_BYTES>>>(go, Wo, bo, (float*)d_out);
}

// round 4
// speedup vs baseline: 3.7509x; 1.1221x over previous
#include <cuda_runtime.h>

#define B_  4
#define T_  2048
#define D_  1024
#define H_  16
#define HD_ 64
#define M_  (B_ * T_)

// Scratch (device globals — no allocations allowed)
__device__ float g_q[B_ * H_ * T_ * HD_];   // [b,h,t,hd']   hd k-permuted
__device__ float g_k[B_ * H_ * T_ * HD_];   // [b,h,t,hd']
__device__ float g_v[B_ * H_ * T_ * HD_];   // [b,h,hd,t']   transposed, t k-permuted
__device__ float g_o[M_ * D_];              // [b*t, d']     d k-permuted, tf32-rounded
__device__ float g_xq[M_ * D_];             // converted+permuted inputs
__device__ float g_xk[M_ * D_];
__device__ float g_xv[M_ * D_];
__device__ float g_wq[D_ * D_];             // converted+permuted weights
__device__ float g_wk[D_ * D_];
__device__ float g_wv[D_ * D_];
__device__ float g_wo[D_ * D_];

// ---------------------------------------------------------------------------
// helpers
// ---------------------------------------------------------------------------
__device__ __forceinline__ unsigned f2tf(float f) {
    unsigned u;
    asm("cvt.rna.tf32.f32 %0, %1;" : "=r"(u) : "f"(f));
    return u;
}
__device__ __forceinline__ float tfr(float f) { return __uint_as_float(f2tf(f)); }
__device__ __forceinline__ int perm8(int k) {
    return (k & ~7) | ((k & 3) << 1) | ((k >> 2) & 1);
}

__device__ __forceinline__ void mma8(float* c, const unsigned* a, const unsigned* b) {
    asm volatile(
        "mma.sync.aligned.m16n8k8.row.col.f32.tf32.tf32.f32 "
        "{%0,%1,%2,%3},{%4,%5,%6,%7},{%8,%9},{%0,%1,%2,%3};"
        : "+f"(c[0]), "+f"(c[1]), "+f"(c[2]), "+f"(c[3])
        : "r"(a[0]), "r"(a[1]), "r"(a[2]), "r"(a[3]), "r"(b[0]), "r"(b[1]));
}

__device__ __forceinline__ void cp16(void* smem_dst, const void* gmem_src) {
    unsigned s = (unsigned)__cvta_generic_to_shared(smem_dst);
    asm volatile("cp.async.cg.shared.global [%0], [%1], 16;\n" :: "r"(s), "l"(gmem_src));
}
#define CP_COMMIT()  asm volatile("cp.async.commit_group;\n" ::: "memory")
#define CP_WAIT(n)   asm volatile("cp.async.wait_group %0;\n" :: "n"(n) : "memory")

// ---------------------------------------------------------------------------
// Convert: rna-tf32 round + within-8-group k permutation (flat index; row
// length multiple of 8). out[8g + {0..7}] = in[8g + {0,4,1,5,2,6,3,7}]
// ---------------------------------------------------------------------------
__global__ void convert_perm(const float* __restrict__ in, float* __restrict__ out, int n8)
{
    int g = blockIdx.x * blockDim.x + threadIdx.x;
    if (g >= n8) return;
    const float4* ip = (const float4*)(in + (size_t)g * 8);
    float4 i0 = ip[0], i1 = ip[1];
    float4 o0, o1;
    o0.x = tfr(i0.x); o0.y = tfr(i1.x); o0.z = tfr(i0.y); o0.w = tfr(i1.y);
    o1.x = tfr(i0.z); o1.y = tfr(i1.z); o1.z = tfr(i0.w); o1.w = tfr(i1.w);
    float4* op = (float4*)(out + (size_t)g * 8);
    op[0] = o0; op[1] = o1;
}

// ---------------------------------------------------------------------------
// GEMM: Y = X[M,1024] @ W[N,1024]^T + bias. Inputs pre-rounded + k-permuted.
// 128x128x32 tiles, 8 warps (2x4), warp 64x32. Fragments via LDS.64, no cvt.
// MODE 0: row-major out (d_out). MODE 1: Q/K scatter, hd-permuted, rounded.
// MODE 2: V transposed scatter [bh][hd][t'], t-permuted, rounded.
// ---------------------------------------------------------------------------
#define GSTR 40
#define GS_A(buf, r, k) smg[(buf) * 5120 + (r) * GSTR + (k)]
#define GS_B(buf, r, k) smg[10240 + (buf) * 5120 + (r) * GSTR + (k)]
#define GEMM_SMEM_BYTES (20480 * 4)

template <int MODE>
__global__ __launch_bounds__(256)
void gemm_mma(const float* __restrict__ X,
              const float* __restrict__ W,
              const float* __restrict__ bias,
              float* __restrict__ Y)
{
    extern __shared__ float smg[];
    const int m0 = blockIdx.y * 128, n0 = blockIdx.x * 128;
    const int t = threadIdx.x, wid = t >> 5, lane = t & 31;
    const int wm = wid >> 2, wn = wid & 3;
    const int lr = lane >> 2, lc = lane & 3;

    float acc[4][4][4];
#pragma unroll
    for (int mt = 0; mt < 4; mt++)
#pragma unroll
        for (int nt = 0; nt < 4; nt++)
#pragma unroll
            for (int e = 0; e < 4; e++) acc[mt][nt][e] = 0.f;

#define LOAD_CHUNK(buf, k0)                                                   \
    {                                                                         \
        _Pragma("unroll")                                                     \
        for (int i = 0; i < 4; i++) {                                         \
            int idx = t + i * 256;                                            \
            int r = idx >> 3, kq = (idx & 7) << 2;                            \
            cp16(&GS_A(buf, r, kq), X + (size_t)(m0 + r) * D_ + (k0) + kq);   \
            cp16(&GS_B(buf, r, kq), W + (size_t)(n0 + r) * D_ + (k0) + kq);   \
        }                                                                     \
        CP_COMMIT();                                                          \
    }

    LOAD_CHUNK(0, 0);

    for (int c = 0; c < 32; c++) {
        const int buf = c & 1;
        if (c < 31) { LOAD_CHUNK(buf ^ 1, (c + 1) * 32); CP_WAIT(1); }
        else        { CP_WAIT(0); }
        __syncthreads();

#pragma unroll
        for (int k8 = 0; k8 < 32; k8 += 8) {
            unsigned a[4][4], b[4][2];
#pragma unroll
            for (int mt = 0; mt < 4; mt++) {
                int row = wm * 64 + mt * 16 + lr;
                float2 p0 = *(const float2*)&GS_A(buf, row,     k8 + 2 * lc);
                float2 p1 = *(const float2*)&GS_A(buf, row + 8, k8 + 2 * lc);
                a[mt][0] = __float_as_uint(p0.x);
                a[mt][1] = __float_as_uint(p1.x);
                a[mt][2] = __float_as_uint(p0.y);
                a[mt][3] = __float_as_uint(p1.y);
            }
#pragma unroll
            for (int nt = 0; nt < 4; nt++) {
                int col = wn * 32 + nt * 8 + lr;
                float2 pb = *(const float2*)&GS_B(buf, col, k8 + 2 * lc);
                b[nt][0] = __float_as_uint(pb.x);
                b[nt][1] = __float_as_uint(pb.y);
            }
#pragma unroll
            for (int mt = 0; mt < 4; mt++)
#pragma unroll
                for (int nt = 0; nt < 4; nt++)
                    mma8(acc[mt][nt], a[mt], b[nt]);
        }
        __syncthreads();
    }

    float bv[4][2];
#pragma unroll
    for (int nt = 0; nt < 4; nt++) {
        int col = n0 + wn * 32 + nt * 8 + 2 * lc;
        bv[nt][0] = bias[col];
        bv[nt][1] = bias[col + 1];
    }

#pragma unroll
    for (int mt = 0; mt < 4; mt++) {
#pragma unroll
        for (int nt = 0; nt < 4; nt++) {
            int row = m0 + wm * 64 + mt * 16 + lr;
            int col = n0 + wn * 32 + nt * 8 + 2 * lc;
            if (MODE == 0) {
                float2 v0 = make_float2(acc[mt][nt][0] + bv[nt][0],
                                        acc[mt][nt][1] + bv[nt][1]);
                float2 v1 = make_float2(acc[mt][nt][2] + bv[nt][0],
                                        acc[mt][nt][3] + bv[nt][1]);
                *(float2*)(Y + (size_t)row * D_ + col)       = v0;
                *(float2*)(Y + (size_t)(row + 8) * D_ + col) = v1;
            } else {
                float v00 = tfr(acc[mt][nt][0] + bv[nt][0]);
                float v01 = tfr(acc[mt][nt][1] + bv[nt][1]);
                float v10 = tfr(acc[mt][nt][2] + bv[nt][0]);
                float v11 = tfr(acc[mt][nt][3] + bv[nt][1]);
                int h = col >> 6, hd = col & 63;
                int bb = row >> 11;            // same for row and row+8
                int tt = row & (T_ - 1);
                if (MODE == 1) {
                    int p0 = perm8(hd), p1 = perm8(hd + 1);
                    float* d0 = Y + (((size_t)(bb * H_ + h) * T_ + tt) * HD_);
                    float* d1 = Y + (((size_t)(bb * H_ + h) * T_ + tt + 8) * HD_);
                    d0[p0] = v00; d0[p1] = v01;
                    d1[p0] = v10; d1[p1] = v11;
                } else {                        // MODE 2: V transposed
                    size_t rb = (size_t)(bb * H_ + h) * 64;
                    int pt0 = perm8(tt);
                    int pt1 = perm8(tt + 8);    // = pt0 + 8
                    (Y + (rb + hd)     * T_)[pt0] = v00;
                    (Y + (rb + hd + 1) * T_)[pt0] = v01;
                    (Y + (rb + hd)     * T_)[pt1] = v10;
                    (Y + (rb + hd + 1) * T_)[pt1] = v11;
                }
            }
        }
    }
#undef LOAD_CHUNK
}

// ---------------------------------------------------------------------------
// Causal flash attention. Block = 128 q-rows x one (b,h), TWO q-tiles per
// block (qi, 15-qi) for perfect load balance. 8 warps; warp = 16 q-rows x 64
// KV cols. All operands pre-rounded tf32 + k-pair-permuted -> LDS.64, no cvt.
// ---------------------------------------------------------------------------
#define KS 72
#define ATT_SMEM_FLOATS (4 * 64 * KS)
#define ATT_SMEM_BYTES  (ATT_SMEM_FLOATS * 4)
#define NQ_ (T_ / 128)   // 16

__global__ __launch_bounds__(256)
void attn_mma3(const float* __restrict__ gq,
               const float* __restrict__ gk,
               const float* __restrict__ gv,
               float* __restrict__ go)
{
    extern __shared__ float sm[];
    float* ksm = sm;                   // [2][64][72]
    float* vsm = sm + 2 * 64 * KS;     // [2][64][72]  (V^T tiles)

    const int bh = blockIdx.x;
    const int t = threadIdx.x, w = t >> 5, lane = t & 31;
    const int lr = lane >> 2, lc = lane & 3;
    const int row0 = w * 16 + lr;

    const float* kbase = gk + (size_t)bh * T_ * HD_;
    const float* vbase = gv + (size_t)bh * HD_ * T_;   // [hd][t']
    const int srcA = (lane & ~3) + (lc >> 1);
    const int srcB = srcA + 2;

#define LOADKV(jt, buf)                                                        \
    {                                                                          \
        const float* kp = kbase + (size_t)(jt) * 64 * HD_;                     \
        float* kd = ksm + (buf) * 64 * KS;                                     \
        float* vd = vsm + (buf) * 64 * KS;                                     \
        _Pragma("unroll")                                                      \
        for (int i = 0; i < 4; i++) {                                          \
            int f = t + i * 256;                                               \
            int r = f >> 4, c4 = (f & 15) << 2;                                \
            cp16(kd + r * KS + c4, kp + (size_t)r * HD_ + c4);                 \
            cp16(vd + r * KS + c4, vbase + (size_t)r * T_ + (jt) * 64 + c4);   \
        }                                                                      \
        CP_COMMIT();                                                           \
    }

    for (int pass = 0; pass < 2; pass++) {
        const int qi = pass ? (NQ_ - 1 - (int)blockIdx.y) : (int)blockIdx.y;
        const int q0 = qi * 128;
        const int n_tiles = 2 * qi + 2;

        // Q fragments (pre-rounded, hd-permuted): float2 loads, scale exact 2^-3
        const float* qptr = gq + ((size_t)bh * T_ + q0) * HD_;
        unsigned qa[8][4];
#pragma unroll
        for (int c = 0; c < 8; c++) {
            float2 q0v = *(const float2*)(qptr + (size_t)row0 * HD_ + c * 8 + 2 * lc);
            float2 q1v = *(const float2*)(qptr + (size_t)(row0 + 8) * HD_ + c * 8 + 2 * lc);
            qa[c][0] = __float_as_uint(q0v.x * 0.125f);
            qa[c][1] = __float_as_uint(q1v.x * 0.125f);
            qa[c][2] = __float_as_uint(q0v.y * 0.125f);
            qa[c][3] = __float_as_uint(q1v.y * 0.125f);
        }

        float o[8][4];
#pragma unroll
        for (int nt = 0; nt < 8; nt++)
#pragma unroll
            for (int e = 0; e < 4; e++) o[nt][e] = 0.f;
        float mr0 = -INFINITY, mr1 = -INFINITY, l0 = 0.f, l1 = 0.f;

        __syncthreads();   // smem safe before first load of this pass
        LOADKV(0, 0);

        for (int jt = 0; jt < n_tiles; jt++) {
            CP_WAIT(0);
            __syncthreads();
            if (jt + 1 < n_tiles) LOADKV(jt + 1, (jt + 1) & 1);

            const int buf = jt & 1;
            const int k0 = jt * 64;
            const float* kb = ksm + buf * 64 * KS;
            const float* vb = vsm + buf * 64 * KS;

            if (k0 > q0 + w * 16 + 15) continue;   // warp fully masked

            // ---- S = Q K^T ----
            float s[8][4];
#pragma unroll
            for (int nt = 0; nt < 8; nt++)
#pragma unroll
                for (int e = 0; e < 4; e++) s[nt][e] = 0.f;

#pragma unroll
            for (int c = 0; c < 8; c++) {
#pragma unroll
                for (int nt = 0; nt < 8; nt++) {
                    float2 pb = *(const float2*)(kb + (nt * 8 + lr) * KS + c * 8 + 2 * lc);
                    unsigned b[2] = {__float_as_uint(pb.x), __float_as_uint(pb.y)};
                    mma8(s[nt], qa[c], b);
                }
            }

            // ---- causal mask (last two tiles only) ----
            if (jt >= 2 * qi) {
                const int rg0 = q0 + row0, rg1 = rg0 + 8;
#pragma unroll
                for (int nt = 0; nt < 8; nt++) {
                    int cg = k0 + nt * 8 + 2 * lc;
                    if (cg     > rg0) s[nt][0] = -1e30f;
                    if (cg + 1 > rg0) s[nt][1] = -1e30f;
                    if (cg     > rg1) s[nt][2] = -1e30f;
                    if (cg + 1 > rg1) s[nt][3] = -1e30f;
                }
            }

            // ---- online softmax in registers ----
            float rm0 = -INFINITY, rm1 = -INFINITY;
#pragma unroll
            for (int nt = 0; nt < 8; nt++) {
                rm0 = fmaxf(rm0, fmaxf(s[nt][0], s[nt][1]));
                rm1 = fmaxf(rm1, fmaxf(s[nt][2], s[nt][3]));
            }
            rm0 = fmaxf(rm0, __shfl_xor_sync(0xffffffffu, rm0, 1));
            rm0 = fmaxf(rm0, __shfl_xor_sync(0xffffffffu, rm0, 2));
            rm1 = fmaxf(rm1, __shfl_xor_sync(0xffffffffu, rm1, 1));
            rm1 = fmaxf(rm1, __shfl_xor_sync(0xffffffffu, rm1, 2));

            float mn0 = fmaxf(mr0, rm0), mn1 = fmaxf(mr1, rm1);
            float al0 = __expf(mr0 - mn0), al1 = __expf(mr1 - mn1);
            mr0 = mn0; mr1 = mn1;

            unsigned u[8][4];
            float rs0 = 0.f, rs1 = 0.f;
#pragma unroll
            for (int nt = 0; nt < 8; nt++) {
                float p0 = __expf(s[nt][0] - mn0);
                float p1 = __expf(s[nt][1] - mn0);
                float p2 = __expf(s[nt][2] - mn1);
                float p3 = __expf(s[nt][3] - mn1);
                rs0 += p0 + p1; rs1 += p2 + p3;
                u[nt][0] = f2tf(p0); u[nt][1] = f2tf(p1);
                u[nt][2] = f2tf(p2); u[nt][3] = f2tf(p3);
            }
            rs0 += __shfl_xor_sync(0xffffffffu, rs0, 1);
            rs0 += __shfl_xor_sync(0xffffffffu, rs0, 2);
            rs1 += __shfl_xor_sync(0xffffffffu, rs1, 1);
            rs1 += __shfl_xor_sync(0xffffffffu, rs1, 2);

            l0 = l0 * al0 + rs0;
            l1 = l1 * al1 + rs1;
#pragma unroll
            for (int nt = 0; nt < 8; nt++) {
                o[nt][0] *= al0; o[nt][1] *= al0;
                o[nt][2] *= al1; o[nt][3] *= al1;
            }

            // ---- O += P V  (P: C-layout -> A-layout via quad shuffles) ----
#pragma unroll
            for (int c = 0; c < 8; c++) {
                unsigned a[4], x0, x1;
                x0 = __shfl_sync(0xffffffffu, u[c][0], srcA);
                x1 = __shfl_sync(0xffffffffu, u[c][1], srcA);
                a[0] = (lc & 1) ? x1 : x0;
                x0 = __shfl_sync(0xffffffffu, u[c][2], srcA);
                x1 = __shfl_sync(0xffffffffu, u[c][3], srcA);
                a[1] = (lc & 1) ? x1 : x0;
                x0 = __shfl_sync(0xffffffffu, u[c][0], srcB);
                x1 = __shfl_sync(0xffffffffu, u[c][1], srcB);
                a[2] = (lc & 1) ? x1 : x0;
                x0 = __shfl_sync(0xffffffffu, u[c][2], srcB);
                x1 = __shfl_sync(0xffffffffu, u[c][3], srcB);
                a[3] = (lc & 1) ? x1 : x0;

#pragma unroll
                for (int nt = 0; nt < 8; nt++) {
                    float2 pv = *(const float2*)(vb + (nt * 8 + lr) * KS + c * 8 + 2 * lc);
                    unsigned b[2] = {__float_as_uint(pv.x), __float_as_uint(pv.y)};
                    mma8(o[nt], a, b);
                }
            }
        }

        // ---- epilogue: normalize, rna-round, write k-permuted [b*t, d'] ----
        const int bb = bh >> 4, h = bh & 15;
        const float inv0 = 1.0f / l0, inv1 = 1.0f / l1;
        const int grow0 = q0 + row0;
#pragma unroll
        for (int nt = 0; nt < 8; nt++) {
            int colb = nt * 8 + 2 * lc;
            int p0 = perm8(colb), p1 = perm8(colb + 1);
            float* d0 = go + (size_t)(bb * T_ + grow0) * D_ + h * 64;
            float* d1 = go + (size_t)(bb * T_ + grow0 + 8) * D_ + h * 64;
            d0[p0] = tfr(o[nt][0] * inv0); d0[p1] = tfr(o[nt][1] * inv0);
            d1[p0] = tfr(o[nt][2] * inv1); d1[p1] = tfr(o[nt][3] * inv1);
        }
    }
#undef LOADKV
}

// ---------------------------------------------------------------------------
extern "C" void kernel_launch(void* const* d_in, const int* in_sizes, int n_in,
                              void* d_out, int out_size)
{
    (void)in_sizes; (void)n_in; (void)out_size;
    const float* Qin = (const float*)d_in[0];
    const float* Kin = (const float*)d_in[1];
    const float* Vin = (const float*)d_in[2];
    // d_in[3] = mask (causal, hardcoded)
    const float* Wq = (const float*)d_in[4];
    const float* bq = (const float*)d_in[5];
    const float* Wk = (const float*)d_in[6];
    const float* bk = (const float*)d_in[7];
    const float* Wv = (const float*)d_in[8];
    const float* bv = (const float*)d_in[9];
    const float* Wo = (const float*)d_in[10];
    const float* bo = (const float*)d_in[11];

    float *gq, *gk, *gv, *go, *xq, *xk, *xv, *wq, *wk, *wv, *wo;
    cudaGetSymbolAddress((void**)&gq, g_q);
    cudaGetSymbolAddress((void**)&gk, g_k);
    cudaGetSymbolAddress((void**)&gv, g_v);
    cudaGetSymbolAddress((void**)&go, g_o);
    cudaGetSymbolAddress((void**)&xq, g_xq);
    cudaGetSymbolAddress((void**)&xk, g_xk);
    cudaGetSymbolAddress((void**)&xv, g_xv);
    cudaGetSymbolAddress((void**)&wq, g_wq);
    cudaGetSymbolAddress((void**)&wk, g_wk);
    cudaGetSymbolAddress((void**)&wv, g_wv);
    cudaGetSymbolAddress((void**)&wo, g_wo);

    cudaFuncSetAttribute(gemm_mma<0>, cudaFuncAttributeMaxDynamicSharedMemorySize, GEMM_SMEM_BYTES);
    cudaFuncSetAttribute(gemm_mma<1>, cudaFuncAttributeMaxDynamicSharedMemorySize, GEMM_SMEM_BYTES);
    cudaFuncSetAttribute(gemm_mma<2>, cudaFuncAttributeMaxDynamicSharedMemorySize, GEMM_SMEM_BYTES);
    cudaFuncSetAttribute(attn_mma3,   cudaFuncAttributeMaxDynamicSharedMemorySize, ATT_SMEM_BYTES);

    const int NX8 = M_ * D_ / 8;   // 1048576
    const int NW8 = D_ * D_ / 8;   // 131072
    convert_perm<<<NX8 / 256, 256>>>(Qin, xq, NX8);
    convert_perm<<<NX8 / 256, 256>>>(Kin, xk, NX8);
    convert_perm<<<NX8 / 256, 256>>>(Vin, xv, NX8);
    convert_perm<<<NW8 / 256, 256>>>(Wq, wq, NW8);
    convert_perm<<<NW8 / 256, 256>>>(Wk, wk, NW8);
    convert_perm<<<NW8 / 256, 256>>>(Wv, wv, NW8);
    convert_perm<<<NW8 / 256, 256>>>(Wo, wo, NW8);

    dim3 gridG(D_ / 128, M_ / 128);   // (8, 64)
    gemm_mma<1><<<gridG, 256, GEMM_SMEM_BYTES>>>(xq, wq, bq, gq);
    gemm_mma<1><<<gridG, 256, GEMM_SMEM_BYTES>>>(xk, wk, bk, gk);
    gemm_mma<2><<<gridG, 256, GEMM_SMEM_BYTES>>>(xv, wv, bv, gv);

    attn_mma3<<<dim3(B_ * H_, NQ_ / 2), 256, ATT_SMEM_BYTES>>>(gq, gk, gv, go);

    gemm_mma<0><<<gridG, 256, GEMM_SMEM_BYTES>>>(go, wo, bo, (float*)d_out);
}

// round 5
// speedup vs baseline: 3.8080x; 1.0152x over previous
#include <cuda_runtime.h>

#define B_  4
#define T_  2048
#define D_  1024
#define H_  16
#define HD_ 64
#define M_  (B_ * T_)

// Scratch (device globals — no allocations allowed)
__device__ float g_q[B_ * H_ * T_ * HD_];   // [b,h,t,hd']   hd perm16
__device__ float g_k[B_ * H_ * T_ * HD_];   // [b,h,t,hd']
__device__ float g_v[B_ * H_ * T_ * HD_];   // [b,h,hd,t']   transposed, t perm16
__device__ float g_o[M_ * D_];              // [b*t, d']     d perm16, tf32-rounded
__device__ float g_xq[M_ * D_];             // converted+perm16 inputs
__device__ float g_xk[M_ * D_];
__device__ float g_xv[M_ * D_];
__device__ float g_wq[D_ * D_];             // converted+perm16 weights
__device__ float g_wk[D_ * D_];
__device__ float g_wv[D_ * D_];
__device__ float g_wo[D_ * D_];

// ---------------------------------------------------------------------------
// helpers
// ---------------------------------------------------------------------------
__device__ __forceinline__ unsigned f2tf(float f) {
    unsigned u;
    asm("cvt.rna.tf32.f32 %0, %1;" : "=r"(u) : "f"(f));
    return u;
}
__device__ __forceinline__ float tfr(float f) { return __uint_as_float(f2tf(f)); }
__device__ __forceinline__ unsigned fu(float f) { return __float_as_uint(f); }
// perm16: element k stored at pos = (k&~15) | 4*(k%4) + k/4  (within 16-group)
__device__ __forceinline__ int pos16(int k) {
    return (k & ~15) | ((k & 3) << 2) | ((k >> 2) & 3);
}

__device__ __forceinline__ void mma8(float* c, const unsigned* a, const unsigned* b) {
    asm volatile(
        "mma.sync.aligned.m16n8k8.row.col.f32.tf32.tf32.f32 "
        "{%0,%1,%2,%3},{%4,%5,%6,%7},{%8,%9},{%0,%1,%2,%3};"
        : "+f"(c[0]), "+f"(c[1]), "+f"(c[2]), "+f"(c[3])
        : "r"(a[0]), "r"(a[1]), "r"(a[2]), "r"(a[3]), "r"(b[0]), "r"(b[1]));
}

__device__ __forceinline__ void cp16(void* smem_dst, const void* gmem_src) {
    unsigned s = (unsigned)__cvta_generic_to_shared(smem_dst);
    asm volatile("cp.async.cg.shared.global [%0], [%1], 16;\n" :: "r"(s), "l"(gmem_src));
}
#define CP_COMMIT()  asm volatile("cp.async.commit_group;\n" ::: "memory")
#define CP_WAIT(n)   asm volatile("cp.async.wait_group %0;\n" :: "n"(n) : "memory")

// ---------------------------------------------------------------------------
// Converts: rna-tf32 round + perm16 (4x4 transpose within each 16-group).
// Fused: one kernel for the 3 inputs, one for the 4 weights.
// ---------------------------------------------------------------------------
__device__ __forceinline__ void conv16(const float* in, float* out, size_t idx)
{
    const float4* ip = (const float4*)(in + idx * 16);
    float4 v0 = ip[0], v1 = ip[1], v2 = ip[2], v3 = ip[3];
    float4* op = (float4*)(out + idx * 16);
    op[0] = make_float4(tfr(v0.x), tfr(v1.x), tfr(v2.x), tfr(v3.x));
    op[1] = make_float4(tfr(v0.y), tfr(v1.y), tfr(v2.y), tfr(v3.y));
    op[2] = make_float4(tfr(v0.z), tfr(v1.z), tfr(v2.z), tfr(v3.z));
    op[3] = make_float4(tfr(v0.w), tfr(v1.w), tfr(v2.w), tfr(v3.w));
}

__global__ void convert_x3(const float* __restrict__ i0, const float* __restrict__ i1,
                           const float* __restrict__ i2,
                           float* __restrict__ o0, float* __restrict__ o1,
                           float* __restrict__ o2)
{
    int g = blockIdx.x * blockDim.x + threadIdx.x;    // 3 * 2^19
    int which = g >> 19;
    size_t idx = (size_t)(g & ((1 << 19) - 1));
    const float* in = which == 0 ? i0 : (which == 1 ? i1 : i2);
    float*      out = which == 0 ? o0 : (which == 1 ? o1 : o2);
    conv16(in, out, idx);
}

__global__ void convert_w4(const float* __restrict__ i0, const float* __restrict__ i1,
                           const float* __restrict__ i2, const float* __restrict__ i3,
                           float* __restrict__ o0, float* __restrict__ o1,
                           float* __restrict__ o2, float* __restrict__ o3)
{
    int g = blockIdx.x * blockDim.x + threadIdx.x;    // 4 * 2^16
    int which = g >> 16;
    size_t idx = (size_t)(g & 0xffff);
    const float* in = which == 0 ? i0 : (which == 1 ? i1 : (which == 2 ? i2 : i3));
    float*      out = which == 0 ? o0 : (which == 1 ? o1 : (which == 2 ? o2 : o3));
    conv16(in, out, idx);
}

// ---------------------------------------------------------------------------
// GEMM core: Y = X[M,1024] @ W[N,1024]^T + bias. Inputs pre-rounded + perm16.
// 128x128x32 tiles, 8 warps (2x4), warp 64x32. Fragments via LDS.128
// (one float4 = two k8 chunks). Smem row stride 48 (== 16 mod 32: phase-
// conflict-free for 128-bit loads).
// MODE 0: row-major out. MODE 1: Q/K head scatter (hd perm16, rounded).
// MODE 2: V transposed scatter [bh][hd][t'] (t perm16, rounded).
// ---------------------------------------------------------------------------
#define GSTR 48
#define GS_A(buf, r, k) smg[(buf) * 6144 + (r) * GSTR + (k)]
#define GS_B(buf, r, k) smg[12288 + (buf) * 6144 + (r) * GSTR + (k)]
#define GEMM_SMEM_BYTES (24576 * 4)   // 96 KB

template <int MODE>
__device__ __forceinline__ void gemm_core(const float* __restrict__ X,
                                          const float* __restrict__ W,
                                          const float* __restrict__ bias,
                                          float* __restrict__ Y,
                                          float* smg)
{
    const int m0 = blockIdx.y * 128, n0 = blockIdx.x * 128;
    const int t = threadIdx.x, wid = t >> 5, lane = t & 31;
    const int wm = wid >> 2, wn = wid & 3;
    const int lr = lane >> 2, lc = lane & 3;

    float acc[4][4][4];
#pragma unroll
    for (int mt = 0; mt < 4; mt++)
#pragma unroll
        for (int nt = 0; nt < 4; nt++)
#pragma unroll
            for (int e = 0; e < 4; e++) acc[mt][nt][e] = 0.f;

#define LOAD_CHUNK(buf, k0)                                                   \
    {                                                                         \
        _Pragma("unroll")                                                     \
        for (int i = 0; i < 4; i++) {                                         \
            int idx = t + i * 256;                                            \
            int r = idx >> 3, kq = (idx & 7) << 2;                            \
            cp16(&GS_A(buf, r, kq), X + (size_t)(m0 + r) * D_ + (k0) + kq);   \
            cp16(&GS_B(buf, r, kq), W + (size_t)(n0 + r) * D_ + (k0) + kq);   \
        }                                                                     \
        CP_COMMIT();                                                          \
    }

    LOAD_CHUNK(0, 0);

    for (int c = 0; c < 32; c++) {
        const int buf = c & 1;
        if (c < 31) { LOAD_CHUNK(buf ^ 1, (c + 1) * 32); CP_WAIT(1); }
        else        { CP_WAIT(0); }
        __syncthreads();

#pragma unroll
        for (int kq = 0; kq < 32; kq += 16) {
            float4 A0[4], A1[4], Bf[4];
#pragma unroll
            for (int mt = 0; mt < 4; mt++) {
                int row = wm * 64 + mt * 16 + lr;
                A0[mt] = *(const float4*)&GS_A(buf, row,     kq + 4 * lc);
                A1[mt] = *(const float4*)&GS_A(buf, row + 8, kq + 4 * lc);
            }
#pragma unroll
            for (int nt = 0; nt < 4; nt++) {
                int col = wn * 32 + nt * 8 + lr;
                Bf[nt] = *(const float4*)&GS_B(buf, col, kq + 4 * lc);
            }
            // chunk 0 (k = kq..kq+7 natural)
#pragma unroll
            for (int mt = 0; mt < 4; mt++) {
                unsigned a[4] = {fu(A0[mt].x), fu(A1[mt].x), fu(A0[mt].y), fu(A1[mt].y)};
#pragma unroll
                for (int nt = 0; nt < 4; nt++) {
                    unsigned b[2] = {fu(Bf[nt].x), fu(Bf[nt].y)};
                    mma8(acc[mt][nt], a, b);
                }
            }
            // chunk 1 (k = kq+8..kq+15 natural)
#pragma unroll
            for (int mt = 0; mt < 4; mt++) {
                unsigned a[4] = {fu(A0[mt].z), fu(A1[mt].z), fu(A0[mt].w), fu(A1[mt].w)};
#pragma unroll
                for (int nt = 0; nt < 4; nt++) {
                    unsigned b[2] = {fu(Bf[nt].z), fu(Bf[nt].w)};
                    mma8(acc[mt][nt], a, b);
                }
            }
        }
        __syncthreads();
    }

    float bv[4][2];
#pragma unroll
    for (int nt = 0; nt < 4; nt++) {
        int col = n0 + wn * 32 + nt * 8 + 2 * lc;
        bv[nt][0] = bias[col];
        bv[nt][1] = bias[col + 1];
    }

#pragma unroll
    for (int mt = 0; mt < 4; mt++) {
#pragma unroll
        for (int nt = 0; nt < 4; nt++) {
            int row = m0 + wm * 64 + mt * 16 + lr;
            int col = n0 + wn * 32 + nt * 8 + 2 * lc;
            if (MODE == 0) {
                float2 v0 = make_float2(acc[mt][nt][0] + bv[nt][0],
                                        acc[mt][nt][1] + bv[nt][1]);
                float2 v1 = make_float2(acc[mt][nt][2] + bv[nt][0],
                                        acc[mt][nt][3] + bv[nt][1]);
                *(float2*)(Y + (size_t)row * D_ + col)       = v0;
                *(float2*)(Y + (size_t)(row + 8) * D_ + col) = v1;
            } else {
                float v00 = tfr(acc[mt][nt][0] + bv[nt][0]);
                float v01 = tfr(acc[mt][nt][1] + bv[nt][1]);
                float v10 = tfr(acc[mt][nt][2] + bv[nt][0]);
                float v11 = tfr(acc[mt][nt][3] + bv[nt][1]);
                int h = col >> 6, hd = col & 63;
                int bb = row >> 11;            // same for row and row+8
                int tt = row & (T_ - 1);
                if (MODE == 1) {
                    int p0 = pos16(hd);        // hd even -> hd+1 at p0+4
                    float* d0 = Y + (((size_t)(bb * H_ + h) * T_ + tt) * HD_);
                    float* d1 = Y + (((size_t)(bb * H_ + h) * T_ + tt + 8) * HD_);
                    d0[p0] = v00; d0[p0 + 4] = v01;
                    d1[p0] = v10; d1[p0 + 4] = v11;
                } else {                        // MODE 2: V transposed
                    size_t rb = (size_t)(bb * H_ + h) * 64;
                    int pt0 = pos16(tt);       // tt&15 = lr < 8 -> tt+8 at pt0+2
                    (Y + (rb + hd)     * T_)[pt0]     = v00;
                    (Y + (rb + hd + 1) * T_)[pt0]     = v01;
                    (Y + (rb + hd)     * T_)[pt0 + 2] = v10;
                    (Y + (rb + hd + 1) * T_)[pt0 + 2] = v11;
                }
            }
        }
    }
#undef LOAD_CHUNK
}

__global__ __launch_bounds__(256, 2)
void gemm_out(const float* __restrict__ X, const float* __restrict__ W,
              const float* __restrict__ bias, float* __restrict__ Y)
{
    extern __shared__ float smg[];
    gemm_core<0>(X, W, bias, Y, smg);
}

__global__ __launch_bounds__(256, 2)
void gemm_qkv(const float* __restrict__ xq, const float* __restrict__ xk,
              const float* __restrict__ xv,
              const float* __restrict__ wq, const float* __restrict__ wk,
              const float* __restrict__ wv,
              const float* __restrict__ bq, const float* __restrict__ bk,
              const float* __restrict__ bv,
              float* __restrict__ yq, float* __restrict__ yk, float* __restrict__ yv)
{
    extern __shared__ float smg[];
    if (blockIdx.z == 0)      gemm_core<1>(xq, wq, bq, yq, smg);
    else if (blockIdx.z == 1) gemm_core<1>(xk, wk, bk, yk, smg);
    else                      gemm_core<2>(xv, wv, bv, yv, smg);
}

// ---------------------------------------------------------------------------
// Causal flash attention. Block = 128 q-rows x one (b,h), TWO q-tiles per
// block (qi, 15-qi) for load balance. 8 warps; warp = 16 q-rows x 64 KV cols.
// perm16 operands -> LDS.128 fragments. 3-stage cp.async pipeline.
// Smem stride 80 (== 16 mod 32, phase-conflict-free).
// ---------------------------------------------------------------------------
#define KS 80
#define ATT_STAGE_FLOATS (2 * 64 * KS)            // K tile + V^T tile
#define ATT_SMEM_FLOATS  (3 * ATT_STAGE_FLOATS)
#define ATT_SMEM_BYTES   (ATT_SMEM_FLOATS * 4)    // 120 KB
#define NQ_ (T_ / 128)   // 16

__global__ __launch_bounds__(256)
void attn_mma4(const float* __restrict__ gq,
               const float* __restrict__ gk,
               const float* __restrict__ gv,
               float* __restrict__ go)
{
    extern __shared__ float sm[];   // [3 stages][K 64x80 | V^T 64x80]

    const int bh = blockIdx.x;
    const int t = threadIdx.x, w = t >> 5, lane = t & 31;
    const int lr = lane >> 2, lc = lane & 3;
    const int row0 = w * 16 + lr;

    const float* kbase = gk + (size_t)bh * T_ * HD_;
    const float* vbase = gv + (size_t)bh * HD_ * T_;   // [hd][t']
    const int srcA = (lane & ~3) + (lc >> 1);
    const int srcB = srcA + 2;

#define LOADKV(jt, st)                                                         \
    {                                                                          \
        const float* kp = kbase + (size_t)(jt) * 64 * HD_;                     \
        float* kd = sm + (st) * ATT_STAGE_FLOATS;                              \
        float* vd = kd + 64 * KS;                                              \
        _Pragma("unroll")                                                      \
        for (int i = 0; i < 4; i++) {                                          \
            int f = t + i * 256;                                               \
            int r = f >> 4, c4 = (f & 15) << 2;                                \
            cp16(kd + r * KS + c4, kp + (size_t)r * HD_ + c4);                 \
            cp16(vd + r * KS + c4, vbase + (size_t)r * T_ + (jt) * 64 + c4);   \
        }                                                                      \
        CP_COMMIT();                                                           \
    }

    for (int pass = 0; pass < 2; pass++) {
        const int qi = pass ? (NQ_ - 1 - (int)blockIdx.y) : (int)blockIdx.y;
        const int q0 = qi * 128;
        const int n_tiles = 2 * qi + 2;

        // Q fragments (pre-rounded, hd perm16): float4 loads, exact 2^-3 scale
        const float* qptr = gq + ((size_t)bh * T_ + q0) * HD_;
        unsigned qa[8][4];
#pragma unroll
        for (int c2 = 0; c2 < 4; c2++) {
            float4 q0v = *(const float4*)(qptr + (size_t)row0 * HD_ + c2 * 16 + 4 * lc);
            float4 q1v = *(const float4*)(qptr + (size_t)(row0 + 8) * HD_ + c2 * 16 + 4 * lc);
            qa[2 * c2][0]     = fu(q0v.x * 0.125f);
            qa[2 * c2][1]     = fu(q1v.x * 0.125f);
            qa[2 * c2][2]     = fu(q0v.y * 0.125f);
            qa[2 * c2][3]     = fu(q1v.y * 0.125f);
            qa[2 * c2 + 1][0] = fu(q0v.z * 0.125f);
            qa[2 * c2 + 1][1] = fu(q1v.z * 0.125f);
            qa[2 * c2 + 1][2] = fu(q0v.w * 0.125f);
            qa[2 * c2 + 1][3] = fu(q1v.w * 0.125f);
        }

        float o[8][4];
#pragma unroll
        for (int nt = 0; nt < 8; nt++)
#pragma unroll
            for (int e = 0; e < 4; e++) o[nt][e] = 0.f;
        float mr0 = -INFINITY, mr1 = -INFINITY, l0 = 0.f, l1 = 0.f;

        __syncthreads();   // smem safe before prologue loads of this pass
        LOADKV(0, 0);
        LOADKV(1, 1);      // n_tiles >= 2 always

        for (int jt = 0; jt < n_tiles; jt++) {
            if (jt + 1 < n_tiles) { CP_WAIT(1); } else { CP_WAIT(0); }
            __syncthreads();
            if (jt + 2 < n_tiles) LOADKV(jt + 2, (jt + 2) % 3);

            const int st = jt % 3;
            const int k0 = jt * 64;
            const float* kb = sm + st * ATT_STAGE_FLOATS;
            const float* vb = kb + 64 * KS;

            if (k0 > q0 + w * 16 + 15) continue;   // warp fully masked

            // ---- S = Q K^T ----
            float s[8][4];
#pragma unroll
            for (int nt = 0; nt < 8; nt++)
#pragma unroll
                for (int e = 0; e < 4; e++) s[nt][e] = 0.f;

#pragma unroll
            for (int c2 = 0; c2 < 4; c2++) {
#pragma unroll
                for (int nt = 0; nt < 8; nt++) {
                    float4 kb4 = *(const float4*)(kb + (nt * 8 + lr) * KS + c2 * 16 + 4 * lc);
                    unsigned b0[2] = {fu(kb4.x), fu(kb4.y)};
                    mma8(s[nt], qa[2 * c2], b0);
                    unsigned b1[2] = {fu(kb4.z), fu(kb4.w)};
                    mma8(s[nt], qa[2 * c2 + 1], b1);
                }
            }

            // ---- causal mask (last two tiles only) ----
            if (jt >= 2 * qi) {
                const int rg0 = q0 + row0, rg1 = rg0 + 8;
#pragma unroll
                for (int nt = 0; nt < 8; nt++) {
                    int cg = k0 + nt * 8 + 2 * lc;
                    if (cg     > rg0) s[nt][0] = -1e30f;
                    if (cg + 1 > rg0) s[nt][1] = -1e30f;
                    if (cg     > rg1) s[nt][2] = -1e30f;
                    if (cg + 1 > rg1) s[nt][3] = -1e30f;
                }
            }

            // ---- online softmax in registers ----
            float rm0 = -INFINITY, rm1 = -INFINITY;
#pragma unroll
            for (int nt = 0; nt < 8; nt++) {
                rm0 = fmaxf(rm0, fmaxf(s[nt][0], s[nt][1]));
                rm1 = fmaxf(rm1, fmaxf(s[nt][2], s[nt][3]));
            }
            rm0 = fmaxf(rm0, __shfl_xor_sync(0xffffffffu, rm0, 1));
            rm0 = fmaxf(rm0, __shfl_xor_sync(0xffffffffu, rm0, 2));
            rm1 = fmaxf(rm1, __shfl_xor_sync(0xffffffffu, rm1, 1));
            rm1 = fmaxf(rm1, __shfl_xor_sync(0xffffffffu, rm1, 2));

            float mn0 = fmaxf(mr0, rm0), mn1 = fmaxf(mr1, rm1);
            float al0 = __expf(mr0 - mn0), al1 = __expf(mr1 - mn1);
            mr0 = mn0; mr1 = mn1;

            unsigned u[8][4];
            float rs0 = 0.f, rs1 = 0.f;
#pragma unroll
            for (int nt = 0; nt < 8; nt++) {
                float p0 = __expf(s[nt][0] - mn0);
                float p1 = __expf(s[nt][1] - mn0);
                float p2 = __expf(s[nt][2] - mn1);
                float p3 = __expf(s[nt][3] - mn1);
                rs0 += p0 + p1; rs1 += p2 + p3;
                u[nt][0] = f2tf(p0); u[nt][1] = f2tf(p1);
                u[nt][2] = f2tf(p2); u[nt][3] = f2tf(p3);
            }
            rs0 += __shfl_xor_sync(0xffffffffu, rs0, 1);
            rs0 += __shfl_xor_sync(0xffffffffu, rs0, 2);
            rs1 += __shfl_xor_sync(0xffffffffu, rs1, 1);
            rs1 += __shfl_xor_sync(0xffffffffu, rs1, 2);

            l0 = l0 * al0 + rs0;
            l1 = l1 * al1 + rs1;
#pragma unroll
            for (int nt = 0; nt < 8; nt++) {
                o[nt][0] *= al0; o[nt][1] *= al0;
                o[nt][2] *= al1; o[nt][3] *= al1;
            }

            // ---- O += P V  (P: C-layout -> A-layout via quad shuffles) ----
#pragma unroll
            for (int c2 = 0; c2 < 4; c2++) {
                unsigned aA[4], aB[4], x0, x1;
                // chunk 2*c2
                {
                    const int c = 2 * c2;
                    x0 = __shfl_sync(0xffffffffu, u[c][0], srcA);
                    x1 = __shfl_sync(0xffffffffu, u[c][1], srcA);
                    aA[0] = (lc & 1) ? x1 : x0;
                    x0 = __shfl_sync(0xffffffffu, u[c][2], srcA);
                    x1 = __shfl_sync(0xffffffffu, u[c][3], srcA);
                    aA[1] = (lc & 1) ? x1 : x0;
                    x0 = __shfl_sync(0xffffffffu, u[c][0], srcB);
                    x1 = __shfl_sync(0xffffffffu, u[c][1], srcB);
                    aA[2] = (lc & 1) ? x1 : x0;
                    x0 = __shfl_sync(0xffffffffu, u[c][2], srcB);
                    x1 = __shfl_sync(0xffffffffu, u[c][3], srcB);
                    aA[3] = (lc & 1) ? x1 : x0;
                }
                // chunk 2*c2+1
                {
                    const int c = 2 * c2 + 1;
                    x0 = __shfl_sync(0xffffffffu, u[c][0], srcA);
                    x1 = __shfl_sync(0xffffffffu, u[c][1], srcA);
                    aB[0] = (lc & 1) ? x1 : x0;
                    x0 = __shfl_sync(0xffffffffu, u[c][2], srcA);
                    x1 = __shfl_sync(0xffffffffu, u[c][3], srcA);
                    aB[1] = (lc & 1) ? x1 : x0;
                    x0 = __shfl_sync(0xffffffffu, u[c][0], srcB);
                    x1 = __shfl_sync(0xffffffffu, u[c][1], srcB);
                    aB[2] = (lc & 1) ? x1 : x0;
                    x0 = __shfl_sync(0xffffffffu, u[c][2], srcB);
                    x1 = __shfl_sync(0xffffffffu, u[c][3], srcB);
                    aB[3] = (lc & 1) ? x1 : x0;
                }
#pragma unroll
                for (int nt = 0; nt < 8; nt++) {
                    float4 vb4 = *(const float4*)(vb + (nt * 8 + lr) * KS + c2 * 16 + 4 * lc);
                    unsigned b0[2] = {fu(vb4.x), fu(vb4.y)};
                    mma8(o[nt], aA, b0);
                    unsigned b1[2] = {fu(vb4.z), fu(vb4.w)};
                    mma8(o[nt], aB, b1);
                }
            }
        }

        // ---- epilogue: normalize, rna-round, write perm16 [b*t, d'] ----
        const int bb = bh >> 4, h = bh & 15;
        const float inv0 = 1.0f / l0, inv1 = 1.0f / l1;
        const int grow0 = q0 + row0;
#pragma unroll
        for (int nt = 0; nt < 8; nt++) {
            int colb = nt * 8 + 2 * lc;
            int p0 = pos16(colb);           // colb even -> colb+1 at p0+4
            float* d0 = go + (size_t)(bb * T_ + grow0) * D_ + h * 64;
            float* d1 = go + (size_t)(bb * T_ + grow0 + 8) * D_ + h * 64;
            d0[p0] = tfr(o[nt][0] * inv0); d0[p0 + 4] = tfr(o[nt][1] * inv0);
            d1[p0] = tfr(o[nt][2] * inv1); d1[p0 + 4] = tfr(o[nt][3] * inv1);
        }
    }
#undef LOADKV
}

// ---------------------------------------------------------------------------
extern "C" void kernel_launch(void* const* d_in, const int* in_sizes, int n_in,
                              void* d_out, int out_size)
{
    (void)in_sizes; (void)n_in; (void)out_size;
    const float* Qin = (const float*)d_in[0];
    const float* Kin = (const float*)d_in[1];
    const float* Vin = (const float*)d_in[2];
    // d_in[3] = mask (causal, hardcoded)
    const float* Wq = (const float*)d_in[4];
    const float* bq = (const float*)d_in[5];
    const float* Wk = (const float*)d_in[6];
    const float* bk = (const float*)d_in[7];
    const float* Wv = (const float*)d_in[8];
    const float* bv = (const float*)d_in[9];
    const float* Wo = (const float*)d_in[10];
    const float* bo = (const float*)d_in[11];

    float *gq, *gk, *gv, *go, *xq, *xk, *xv, *wq, *wk, *wv, *wo;
    cudaGetSymbolAddress((void**)&gq, g_q);
    cudaGetSymbolAddress((void**)&gk, g_k);
    cudaGetSymbolAddress((void**)&gv, g_v);
    cudaGetSymbolAddress((void**)&go, g_o);
    cudaGetSymbolAddress((void**)&xq, g_xq);
    cudaGetSymbolAddress((void**)&xk, g_xk);
    cudaGetSymbolAddress((void**)&xv, g_xv);
    cudaGetSymbolAddress((void**)&wq, g_wq);
    cudaGetSymbolAddress((void**)&wk, g_wk);
    cudaGetSymbolAddress((void**)&wv, g_wv);
    cudaGetSymbolAddress((void**)&wo, g_wo);

    cudaFuncSetAttribute(gemm_out,  cudaFuncAttributeMaxDynamicSharedMemorySize, GEMM_SMEM_BYTES);
    cudaFuncSetAttribute(gemm_qkv,  cudaFuncAttributeMaxDynamicSharedMemorySize, GEMM_SMEM_BYTES);
    cudaFuncSetAttribute(attn_mma4, cudaFuncAttributeMaxDynamicSharedMemorySize, ATT_SMEM_BYTES);

    // converts: 3 inputs (3 * 2^19 groups), 4 weights (4 * 2^16 groups)
    convert_x3<<<(3 << 19) / 256, 256>>>(Qin, Kin, Vin, xq, xk, xv);
    convert_w4<<<(4 << 16) / 256, 256>>>(Wq, Wk, Wv, Wo, wq, wk, wv, wo);

    dim3 gridQKV(D_ / 128, M_ / 128, 3);   // (8, 64, 3)
    gemm_qkv<<<gridQKV, 256, GEMM_SMEM_BYTES>>>(xq, xk, xv, wq, wk, wv,
                                                bq, bk, bv, gq, gk, gv);

    attn_mma4<<<dim3(B_ * H_, NQ_ / 2), 256, ATT_SMEM_BYTES>>>(gq, gk, gv, go);

    dim3 gridG(D_ / 128, M_ / 128);        // (8, 64)
    gemm_out<<<gridG, 256, GEMM_SMEM_BYTES>>>(go, wo, bo, (float*)d_out);
}

// round 6
// speedup vs baseline: 3.8163x; 1.0022x over previous
#include <cuda_runtime.h>

#define B_  4
#define T_  2048
#define D_  1024
#define H_  16
#define HD_ 64
#define M_  (B_ * T_)

// Scratch (device globals — no allocations allowed)
__device__ float g_q[B_ * H_ * T_ * HD_];   // [b,h,t,hd']   hd perm16
__device__ float g_k[B_ * H_ * T_ * HD_];   // [b,h,t,hd']
__device__ float g_v[B_ * H_ * T_ * HD_];   // [b,h,hd,t']   transposed, t perm16
__device__ float g_o[M_ * D_];              // [b*t, d']     d perm16, tf32-rounded
__device__ float g_xq[M_ * D_];             // converted+perm16 inputs
__device__ float g_xk[M_ * D_];
__device__ float g_xv[M_ * D_];
__device__ float g_wq[D_ * D_];             // converted+perm16 weights
__device__ float g_wk[D_ * D_];
__device__ float g_wv[D_ * D_];
__device__ float g_wo[D_ * D_];

#define LOG2E 1.4426950408889634f

// ---------------------------------------------------------------------------
// helpers
// ---------------------------------------------------------------------------
__device__ __forceinline__ unsigned f2tf(float f) {
    unsigned u;
    asm("cvt.rna.tf32.f32 %0, %1;" : "=r"(u) : "f"(f));
    return u;
}
__device__ __forceinline__ float tfr(float f) { return __uint_as_float(f2tf(f)); }
__device__ __forceinline__ unsigned fu(float f) { return __float_as_uint(f); }
// perm16: element k stored at pos = (k&~15) | 4*(k%4) + k/4  (within 16-group)
__device__ __forceinline__ int pos16(int k) {
    return (k & ~15) | ((k & 3) << 2) | ((k >> 2) & 3);
}

__device__ __forceinline__ void mma8(float* c, const unsigned* a, const unsigned* b) {
    asm volatile(
        "mma.sync.aligned.m16n8k8.row.col.f32.tf32.tf32.f32 "
        "{%0,%1,%2,%3},{%4,%5,%6,%7},{%8,%9},{%0,%1,%2,%3};"
        : "+f"(c[0]), "+f"(c[1]), "+f"(c[2]), "+f"(c[3])
        : "r"(a[0]), "r"(a[1]), "r"(a[2]), "r"(a[3]), "r"(b[0]), "r"(b[1]));
}

__device__ __forceinline__ void cp16(void* smem_dst, const void* gmem_src) {
    unsigned s = (unsigned)__cvta_generic_to_shared(smem_dst);
    asm volatile("cp.async.cg.shared.global [%0], [%1], 16;\n" :: "r"(s), "l"(gmem_src));
}
#define CP_COMMIT()  asm volatile("cp.async.commit_group;\n" ::: "memory")
#define CP_WAIT(n)   asm volatile("cp.async.wait_group %0;\n" :: "n"(n) : "memory")

// ---------------------------------------------------------------------------
// Converts: rna-tf32 round + perm16 (4x4 transpose within each 16-group).
// ---------------------------------------------------------------------------
__device__ __forceinline__ void conv16(const float* in, float* out, size_t idx)
{
    const float4* ip = (const float4*)(in + idx * 16);
    float4 v0 = ip[0], v1 = ip[1], v2 = ip[2], v3 = ip[3];
    float4* op = (float4*)(out + idx * 16);
    op[0] = make_float4(tfr(v0.x), tfr(v1.x), tfr(v2.x), tfr(v3.x));
    op[1] = make_float4(tfr(v0.y), tfr(v1.y), tfr(v2.y), tfr(v3.y));
    op[2] = make_float4(tfr(v0.z), tfr(v1.z), tfr(v2.z), tfr(v3.z));
    op[3] = make_float4(tfr(v0.w), tfr(v1.w), tfr(v2.w), tfr(v3.w));
}

__global__ void convert_x3(const float* __restrict__ i0, const float* __restrict__ i1,
                           const float* __restrict__ i2,
                           float* __restrict__ o0, float* __restrict__ o1,
                           float* __restrict__ o2)
{
    int g = blockIdx.x * blockDim.x + threadIdx.x;    // 3 * 2^19
    int which = g >> 19;
    size_t idx = (size_t)(g & ((1 << 19) - 1));
    const float* in = which == 0 ? i0 : (which == 1 ? i1 : i2);
    float*      out = which == 0 ? o0 : (which == 1 ? o1 : o2);
    conv16(in, out, idx);
}

__global__ void convert_w4(const float* __restrict__ i0, const float* __restrict__ i1,
                           const float* __restrict__ i2, const float* __restrict__ i3,
                           float* __restrict__ o0, float* __restrict__ o1,
                           float* __restrict__ o2, float* __restrict__ o3)
{
    int g = blockIdx.x * blockDim.x + threadIdx.x;    // 4 * 2^16
    int which = g >> 16;
    size_t idx = (size_t)(g & 0xffff);
    const float* in = which == 0 ? i0 : (which == 1 ? i1 : (which == 2 ? i2 : i3));
    float*      out = which == 0 ? o0 : (which == 1 ? o1 : (which == 2 ? o2 : o3));
    conv16(in, out, idx);
}

// ---------------------------------------------------------------------------
// GEMM core: Y = X[M,1024] @ W[N,1024]^T + bias. Inputs pre-rounded + perm16.
// 128x128x32 tiles, 8 warps (2x4), warp 64x32. Fragments via LDS.128.
// MODE 0: row-major out. MODE 1: Q/K head scatter. MODE 2: V^T scatter.
// ---------------------------------------------------------------------------
#define GSTR 48
#define GS_A(buf, r, k) smg[(buf) * 6144 + (r) * GSTR + (k)]
#define GS_B(buf, r, k) smg[12288 + (buf) * 6144 + (r) * GSTR + (k)]
#define GEMM_SMEM_BYTES (24576 * 4)   // 96 KB

template <int MODE>
__device__ __forceinline__ void gemm_core(const float* __restrict__ X,
                                          const float* __restrict__ W,
                                          const float* __restrict__ bias,
                                          float* __restrict__ Y,
                                          float* smg)
{
    const int m0 = blockIdx.y * 128, n0 = blockIdx.x * 128;
    const int t = threadIdx.x, wid = t >> 5, lane = t & 31;
    const int wm = wid >> 2, wn = wid & 3;
    const int lr = lane >> 2, lc = lane & 3;

    float acc[4][4][4];
#pragma unroll
    for (int mt = 0; mt < 4; mt++)
#pragma unroll
        for (int nt = 0; nt < 4; nt++)
#pragma unroll
            for (int e = 0; e < 4; e++) acc[mt][nt][e] = 0.f;

#define LOAD_CHUNK(buf, k0)                                                   \
    {                                                                         \
        _Pragma("unroll")                                                     \
        for (int i = 0; i < 4; i++) {                                         \
            int idx = t + i * 256;                                            \
            int r = idx >> 3, kq = (idx & 7) << 2;                            \
            cp16(&GS_A(buf, r, kq), X + (size_t)(m0 + r) * D_ + (k0) + kq);   \
            cp16(&GS_B(buf, r, kq), W + (size_t)(n0 + r) * D_ + (k0) + kq);   \
        }                                                                     \
        CP_COMMIT();                                                          \
    }

    LOAD_CHUNK(0, 0);

    for (int c = 0; c < 32; c++) {
        const int buf = c & 1;
        if (c < 31) { LOAD_CHUNK(buf ^ 1, (c + 1) * 32); CP_WAIT(1); }
        else        { CP_WAIT(0); }
        __syncthreads();

#pragma unroll
        for (int kq = 0; kq < 32; kq += 16) {
            float4 A0[4], A1[4], Bf[4];
#pragma unroll
            for (int mt = 0; mt < 4; mt++) {
                int row = wm * 64 + mt * 16 + lr;
                A0[mt] = *(const float4*)&GS_A(buf, row,     kq + 4 * lc);
                A1[mt] = *(const float4*)&GS_A(buf, row + 8, kq + 4 * lc);
            }
#pragma unroll
            for (int nt = 0; nt < 4; nt++) {
                int col = wn * 32 + nt * 8 + lr;
                Bf[nt] = *(const float4*)&GS_B(buf, col, kq + 4 * lc);
            }
#pragma unroll
            for (int mt = 0; mt < 4; mt++) {
                unsigned a[4] = {fu(A0[mt].x), fu(A1[mt].x), fu(A0[mt].y), fu(A1[mt].y)};
#pragma unroll
                for (int nt = 0; nt < 4; nt++) {
                    unsigned b[2] = {fu(Bf[nt].x), fu(Bf[nt].y)};
                    mma8(acc[mt][nt], a, b);
                }
            }
#pragma unroll
            for (int mt = 0; mt < 4; mt++) {
                unsigned a[4] = {fu(A0[mt].z), fu(A1[mt].z), fu(A0[mt].w), fu(A1[mt].w)};
#pragma unroll
                for (int nt = 0; nt < 4; nt++) {
                    unsigned b[2] = {fu(Bf[nt].z), fu(Bf[nt].w)};
                    mma8(acc[mt][nt], a, b);
                }
            }
        }
        __syncthreads();
    }

    float bv[4][2];
#pragma unroll
    for (int nt = 0; nt < 4; nt++) {
        int col = n0 + wn * 32 + nt * 8 + 2 * lc;
        bv[nt][0] = bias[col];
        bv[nt][1] = bias[col + 1];
    }

#pragma unroll
    for (int mt = 0; mt < 4; mt++) {
#pragma unroll
        for (int nt = 0; nt < 4; nt++) {
            int row = m0 + wm * 64 + mt * 16 + lr;
            int col = n0 + wn * 32 + nt * 8 + 2 * lc;
            if (MODE == 0) {
                float2 v0 = make_float2(acc[mt][nt][0] + bv[nt][0],
                                        acc[mt][nt][1] + bv[nt][1]);
                float2 v1 = make_float2(acc[mt][nt][2] + bv[nt][0],
                                        acc[mt][nt][3] + bv[nt][1]);
                *(float2*)(Y + (size_t)row * D_ + col)       = v0;
                *(float2*)(Y + (size_t)(row + 8) * D_ + col) = v1;
            } else {
                float v00 = tfr(acc[mt][nt][0] + bv[nt][0]);
                float v01 = tfr(acc[mt][nt][1] + bv[nt][1]);
                float v10 = tfr(acc[mt][nt][2] + bv[nt][0]);
                float v11 = tfr(acc[mt][nt][3] + bv[nt][1]);
                int h = col >> 6, hd = col & 63;
                int bb = row >> 11;
                int tt = row & (T_ - 1);
                if (MODE == 1) {
                    int p0 = pos16(hd);        // hd even -> hd+1 at p0+4
                    float* d0 = Y + (((size_t)(bb * H_ + h) * T_ + tt) * HD_);
                    float* d1 = Y + (((size_t)(bb * H_ + h) * T_ + tt + 8) * HD_);
                    d0[p0] = v00; d0[p0 + 4] = v01;
                    d1[p0] = v10; d1[p0 + 4] = v11;
                } else {                        // MODE 2: V transposed
                    size_t rb = (size_t)(bb * H_ + h) * 64;
                    int pt0 = pos16(tt);       // tt&15 = lr < 8 -> tt+8 at pt0+2
                    (Y + (rb + hd)     * T_)[pt0]     = v00;
                    (Y + (rb + hd + 1) * T_)[pt0]     = v01;
                    (Y + (rb + hd)     * T_)[pt0 + 2] = v10;
                    (Y + (rb + hd + 1) * T_)[pt0 + 2] = v11;
                }
            }
        }
    }
#undef LOAD_CHUNK
}

__global__ __launch_bounds__(256, 2)
void gemm_out(const float* __restrict__ X, const float* __restrict__ W,
              const float* __restrict__ bias, float* __restrict__ Y)
{
    extern __shared__ float smg[];
    gemm_core<0>(X, W, bias, Y, smg);
}

__global__ __launch_bounds__(256, 2)
void gemm_qkv(const float* __restrict__ xq, const float* __restrict__ xk,
              const float* __restrict__ xv,
              const float* __restrict__ wq, const float* __restrict__ wk,
              const float* __restrict__ wv,
              const float* __restrict__ bq, const float* __restrict__ bk,
              const float* __restrict__ bv,
              float* __restrict__ yq, float* __restrict__ yk, float* __restrict__ yv)
{
    extern __shared__ float smg[];
    if (blockIdx.z == 0)      gemm_core<1>(xq, wq, bq, yq, smg);
    else if (blockIdx.z == 1) gemm_core<1>(xk, wk, bk, yk, smg);
    else                      gemm_core<2>(xv, wv, bv, yv, smg);
}

// ---------------------------------------------------------------------------
// Causal flash attention. Block = 128 q-rows x one (b,h), TWO q-tiles per
// block (qi, 15-qi). 8 warps; warp = 16 q-rows x 64 KV cols.
// Register diet for 2 CTAs/SM: P converted in place inside s (no u array),
// launch_bounds(256,2). 2-stage cp.async pipeline (80 KB smem).
// Softmax in exp2 domain: Q scale = 0.125*log2(e), bare EX2 for exponentials.
// ---------------------------------------------------------------------------
#define KS 80
#define ATT_STAGE_FLOATS (2 * 64 * KS)            // K tile + V^T tile
#define ATT_SMEM_FLOATS  (2 * ATT_STAGE_FLOATS)
#define ATT_SMEM_BYTES   (ATT_SMEM_FLOATS * 4)    // 80 KB
#define NQ_ (T_ / 128)   // 16

__global__ __launch_bounds__(256, 2)
void attn_mma5(const float* __restrict__ gq,
               const float* __restrict__ gk,
               const float* __restrict__ gv,
               float* __restrict__ go)
{
    extern __shared__ float sm[];   // [2 stages][K 64x80 | V^T 64x80]

    const int bh = blockIdx.x;
    const int t = threadIdx.x, w = t >> 5, lane = t & 31;
    const int lr = lane >> 2, lc = lane & 3;
    const int row0 = w * 16 + lr;

    const float* kbase = gk + (size_t)bh * T_ * HD_;
    const float* vbase = gv + (size_t)bh * HD_ * T_;   // [hd][t']
    const int srcA = (lane & ~3) + (lc >> 1);
    const int srcB = srcA + 2;

#define LOADKV(jt, st)                                                         \
    {                                                                          \
        const float* kp = kbase + (size_t)(jt) * 64 * HD_;                     \
        float* kd = sm + (st) * ATT_STAGE_FLOATS;                              \
        float* vd = kd + 64 * KS;                                              \
        _Pragma("unroll")                                                      \
        for (int i = 0; i < 4; i++) {                                          \
            int f = t + i * 256;                                               \
            int r = f >> 4, c4 = (f & 15) << 2;                                \
            cp16(kd + r * KS + c4, kp + (size_t)r * HD_ + c4);                 \
            cp16(vd + r * KS + c4, vbase + (size_t)r * T_ + (jt) * 64 + c4);   \
        }                                                                      \
        CP_COMMIT();                                                           \
    }

    for (int pass = 0; pass < 2; pass++) {
        const int qi = pass ? (NQ_ - 1 - (int)blockIdx.y) : (int)blockIdx.y;
        const int q0 = qi * 128;
        const int n_tiles = 2 * qi + 2;

        // Q fragments (pre-rounded, hd perm16); scale folds 1/8 * log2(e)
        const float* qptr = gq + ((size_t)bh * T_ + q0) * HD_;
        const float qs = 0.125f * LOG2E;
        unsigned qa[8][4];
#pragma unroll
        for (int c2 = 0; c2 < 4; c2++) {
            float4 q0v = *(const float4*)(qptr + (size_t)row0 * HD_ + c2 * 16 + 4 * lc);
            float4 q1v = *(const float4*)(qptr + (size_t)(row0 + 8) * HD_ + c2 * 16 + 4 * lc);
            qa[2 * c2][0]     = fu(q0v.x * qs);
            qa[2 * c2][1]     = fu(q1v.x * qs);
            qa[2 * c2][2]     = fu(q0v.y * qs);
            qa[2 * c2][3]     = fu(q1v.y * qs);
            qa[2 * c2 + 1][0] = fu(q0v.z * qs);
            qa[2 * c2 + 1][1] = fu(q1v.z * qs);
            qa[2 * c2 + 1][2] = fu(q0v.w * qs);
            qa[2 * c2 + 1][3] = fu(q1v.w * qs);
        }

        float o[8][4];
#pragma unroll
        for (int nt = 0; nt < 8; nt++)
#pragma unroll
            for (int e = 0; e < 4; e++) o[nt][e] = 0.f;
        float mr0 = -INFINITY, mr1 = -INFINITY, l0 = 0.f, l1 = 0.f;

        __syncthreads();   // smem safe before prologue load of this pass
        LOADKV(0, 0);

        for (int jt = 0; jt < n_tiles; jt++) {
            CP_WAIT(0);
            __syncthreads();
            if (jt + 1 < n_tiles) LOADKV(jt + 1, (jt + 1) & 1);

            const int st = jt & 1;
            const int k0 = jt * 64;
            const float* kb = sm + st * ATT_STAGE_FLOATS;
            const float* vb = kb + 64 * KS;

            if (k0 > q0 + w * 16 + 15) continue;   // warp fully masked

            // ---- S = Q K^T  (log2-domain scores) ----
            float s[8][4];
#pragma unroll
            for (int nt = 0; nt < 8; nt++)
#pragma unroll
                for (int e = 0; e < 4; e++) s[nt][e] = 0.f;

#pragma unroll
            for (int c2 = 0; c2 < 4; c2++) {
#pragma unroll
                for (int nt = 0; nt < 8; nt++) {
                    float4 kb4 = *(const float4*)(kb + (nt * 8 + lr) * KS + c2 * 16 + 4 * lc);
                    unsigned b0[2] = {fu(kb4.x), fu(kb4.y)};
                    mma8(s[nt], qa[2 * c2], b0);
                    unsigned b1[2] = {fu(kb4.z), fu(kb4.w)};
                    mma8(s[nt], qa[2 * c2 + 1], b1);
                }
            }

            // ---- causal mask (last two tiles only) ----
            if (jt >= 2 * qi) {
                const int rg0 = q0 + row0, rg1 = rg0 + 8;
#pragma unroll
                for (int nt = 0; nt < 8; nt++) {
                    int cg = k0 + nt * 8 + 2 * lc;
                    if (cg     > rg0) s[nt][0] = -1e30f;
                    if (cg + 1 > rg0) s[nt][1] = -1e30f;
                    if (cg     > rg1) s[nt][2] = -1e30f;
                    if (cg + 1 > rg1) s[nt][3] = -1e30f;
                }
            }

            // ---- online softmax (exp2 domain) ----
            float rm0 = -INFINITY, rm1 = -INFINITY;
#pragma unroll
            for (int nt = 0; nt < 8; nt++) {
                rm0 = fmaxf(rm0, fmaxf(s[nt][0], s[nt][1]));
                rm1 = fmaxf(rm1, fmaxf(s[nt][2], s[nt][3]));
            }
            rm0 = fmaxf(rm0, __shfl_xor_sync(0xffffffffu, rm0, 1));
            rm0 = fmaxf(rm0, __shfl_xor_sync(0xffffffffu, rm0, 2));
            rm1 = fmaxf(rm1, __shfl_xor_sync(0xffffffffu, rm1, 1));
            rm1 = fmaxf(rm1, __shfl_xor_sync(0xffffffffu, rm1, 2));

            float mn0 = fmaxf(mr0, rm0), mn1 = fmaxf(mr1, rm1);
            float al0 = exp2f(mr0 - mn0), al1 = exp2f(mr1 - mn1);
            mr0 = mn0; mr1 = mn1;

            float rs0 = 0.f, rs1 = 0.f;
#pragma unroll
            for (int nt = 0; nt < 8; nt++) {
                float p0 = exp2f(s[nt][0] - mn0);
                float p1 = exp2f(s[nt][1] - mn0);
                float p2 = exp2f(s[nt][2] - mn1);
                float p3 = exp2f(s[nt][3] - mn1);
                rs0 += p0 + p1; rs1 += p2 + p3;
                // convert in place: s now holds tf32 bit patterns of P
                s[nt][0] = __uint_as_float(f2tf(p0));
                s[nt][1] = __uint_as_float(f2tf(p1));
                s[nt][2] = __uint_as_float(f2tf(p2));
                s[nt][3] = __uint_as_float(f2tf(p3));
            }
            rs0 += __shfl_xor_sync(0xffffffffu, rs0, 1);
            rs0 += __shfl_xor_sync(0xffffffffu, rs0, 2);
            rs1 += __shfl_xor_sync(0xffffffffu, rs1, 1);
            rs1 += __shfl_xor_sync(0xffffffffu, rs1, 2);

            l0 = l0 * al0 + rs0;
            l1 = l1 * al1 + rs1;
#pragma unroll
            for (int nt = 0; nt < 8; nt++) {
                o[nt][0] *= al0; o[nt][1] *= al0;
                o[nt][2] *= al1; o[nt][3] *= al1;
            }

            // ---- O += P V  (P bits in s; C-layout -> A-layout via shuffles) ----
#pragma unroll
            for (int c2 = 0; c2 < 4; c2++) {
                unsigned aA[4], aB[4];
                float x0, x1;
                {
                    const int c = 2 * c2;
                    x0 = __shfl_sync(0xffffffffu, s[c][0], srcA);
                    x1 = __shfl_sync(0xffffffffu, s[c][1], srcA);
                    aA[0] = fu((lc & 1) ? x1 : x0);
                    x0 = __shfl_sync(0xffffffffu, s[c][2], srcA);
                    x1 = __shfl_sync(0xffffffffu, s[c][3], srcA);
                    aA[1] = fu((lc & 1) ? x1 : x0);
                    x0 = __shfl_sync(0xffffffffu, s[c][0], srcB);
                    x1 = __shfl_sync(0xffffffffu, s[c][1], srcB);
                    aA[2] = fu((lc & 1) ? x1 : x0);
                    x0 = __shfl_sync(0xffffffffu, s[c][2], srcB);
                    x1 = __shfl_sync(0xffffffffu, s[c][3], srcB);
                    aA[3] = fu((lc & 1) ? x1 : x0);
                }
                {
                    const int c = 2 * c2 + 1;
                    x0 = __shfl_sync(0xffffffffu, s[c][0], srcA);
                    x1 = __shfl_sync(0xffffffffu, s[c][1], srcA);
                    aB[0] = fu((lc & 1) ? x1 : x0);
                    x0 = __shfl_sync(0xffffffffu, s[c][2], srcA);
                    x1 = __shfl_sync(0xffffffffu, s[c][3], srcA);
                    aB[1] = fu((lc & 1) ? x1 : x0);
                    x0 = __shfl_sync(0xffffffffu, s[c][0], srcB);
                    x1 = __shfl_sync(0xffffffffu, s[c][1], srcB);
                    aB[2] = fu((lc & 1) ? x1 : x0);
                    x0 = __shfl_sync(0xffffffffu, s[c][2], srcB);
                    x1 = __shfl_sync(0xffffffffu, s[c][3], srcB);
                    aB[3] = fu((lc & 1) ? x1 : x0);
                }
#pragma unroll
                for (int nt = 0; nt < 8; nt++) {
                    float4 vb4 = *(const float4*)(vb + (nt * 8 + lr) * KS + c2 * 16 + 4 * lc);
                    unsigned b0[2] = {fu(vb4.x), fu(vb4.y)};
                    mma8(o[nt], aA, b0);
                    unsigned b1[2] = {fu(vb4.z), fu(vb4.w)};
                    mma8(o[nt], aB, b1);
                }
            }
        }

        // ---- epilogue: normalize, rna-round, write perm16 [b*t, d'] ----
        const int bb = bh >> 4, h = bh & 15;
        const float inv0 = 1.0f / l0, inv1 = 1.0f / l1;
        const int grow0 = q0 + row0;
#pragma unroll
        for (int nt = 0; nt < 8; nt++) {
            int colb = nt * 8 + 2 * lc;
            int p0 = pos16(colb);           // colb even -> colb+1 at p0+4
            float* d0 = go + (size_t)(bb * T_ + grow0) * D_ + h * 64;
            float* d1 = go + (size_t)(bb * T_ + grow0 + 8) * D_ + h * 64;
            d0[p0] = tfr(o[nt][0] * inv0); d0[p0 + 4] = tfr(o[nt][1] * inv0);
            d1[p0] = tfr(o[nt][2] * inv1); d1[p0 + 4] = tfr(o[nt][3] * inv1);
        }
    }
#undef LOADKV
}

// ---------------------------------------------------------------------------
extern "C" void kernel_launch(void* const* d_in, const int* in_sizes, int n_in,
                              void* d_out, int out_size)
{
    (void)in_sizes; (void)n_in; (void)out_size;
    const float* Qin = (const float*)d_in[0];
    const float* Kin = (const float*)d_in[1];
    const float* Vin = (const float*)d_in[2];
    // d_in[3] = mask (causal, hardcoded)
    const float* Wq = (const float*)d_in[4];
    const float* bq = (const float*)d_in[5];
    const float* Wk = (const float*)d_in[6];
    const float* bk = (const float*)d_in[7];
    const float* Wv = (const float*)d_in[8];
    const float* bv = (const float*)d_in[9];
    const float* Wo = (const float*)d_in[10];
    const float* bo = (const float*)d_in[11];

    float *gq, *gk, *gv, *go, *xq, *xk, *xv, *wq, *wk, *wv, *wo;
    cudaGetSymbolAddress((void**)&gq, g_q);
    cudaGetSymbolAddress((void**)&gk, g_k);
    cudaGetSymbolAddress((void**)&gv, g_v);
    cudaGetSymbolAddress((void**)&go, g_o);
    cudaGetSymbolAddress((void**)&xq, g_xq);
    cudaGetSymbolAddress((void**)&xk, g_xk);
    cudaGetSymbolAddress((void**)&xv, g_xv);
    cudaGetSymbolAddress((void**)&wq, g_wq);
    cudaGetSymbolAddress((void**)&wk, g_wk);
    cudaGetSymbolAddress((void**)&wv, g_wv);
    cudaGetSymbolAddress((void**)&wo, g_wo);

    cudaFuncSetAttribute(gemm_out,  cudaFuncAttributeMaxDynamicSharedMemorySize, GEMM_SMEM_BYTES);
    cudaFuncSetAttribute(gemm_qkv,  cudaFuncAttributeMaxDynamicSharedMemorySize, GEMM_SMEM_BYTES);
    cudaFuncSetAttribute(attn_mma5, cudaFuncAttributeMaxDynamicSharedMemorySize, ATT_SMEM_BYTES);

    convert_x3<<<(3 << 19) / 256, 256>>>(Qin, Kin, Vin, xq, xk, xv);
    convert_w4<<<(4 << 16) / 256, 256>>>(Wq, Wk, Wv, Wo, wq, wk, wv, wo);

    dim3 gridQKV(D_ / 128, M_ / 128, 3);   // (8, 64, 3)
    gemm_qkv<<<gridQKV, 256, GEMM_SMEM_BYTES>>>(xq, xk, xv, wq, wk, wv,
                                                bq, bk, bv, gq, gk, gv);

    attn_mma5<<<dim3(B_ * H_, NQ_ / 2), 256, ATT_SMEM_BYTES>>>(gq, gk, gv, go);

    dim3 gridG(D_ / 128, M_ / 128);        // (8, 64)
    gemm_out<<<gridG, 256, GEMM_SMEM_BYTES>>>(go, wo, bo, (float*)d_out);
}